// round 8
// baseline (speedup 1.0000x reference)
#include <cuda_runtime.h>
#include <cuda_fp16.h>

#define NMAX   100000
#define EMAX   1200000
#define NGRAPH 64
#define D      64
#define NBLK_SCAN 128   // >= ceil(NMAX/1024)

// ---------------- device scratch (no allocations allowed) ----------------
// INVARIANT: g_cntI, g_pooled, g_cnt are ZERO at entry to every call.
// g_lbFlag is reset by k_cnt (block 0) before k_scanLB runs.
__device__ __align__(16) __half g_hH[(size_t)NMAX * D];   // pre-agg rows (fp16)
__device__ __align__(16) __half g_hG[(size_t)NMAX * D];   // h1 rows (fp16)
__device__ float g_dinv[NMAX];
__device__ __align__(16) float g_pooled[NGRAPH * D];
__device__ float g_cnt[NGRAPH];
__device__ float g_sc1[D], g_sh1[D], g_sc2[D], g_sh2[D];

__device__ int g_cntI[NMAX];
__device__ int g_offs[NMAX + 1];
__device__ int g_cursor[NMAX];
__device__ __align__(16) int g_csrc[EMAX];
__device__ volatile unsigned g_lbFlag[NBLK_SCAN];  // status(2b)<<30 | sum

__device__ __forceinline__ void red_add_v2(float* addr, float a, float b) {
    asm volatile("red.global.add.v2.f32 [%0], {%1,%2};"
                 :: "l"(addr), "f"(a), "f"(b) : "memory");
}

__device__ __forceinline__ float2 h2f(unsigned raw) {
    return __half22float2(*(__half2*)&raw);
}

__device__ __forceinline__ unsigned f2h(float a, float b) {
    __half2 p = __floats2half2_rn(a, b);
    return *(unsigned*)&p;
}

__device__ __forceinline__ uint2 f4_to_h4(float a, float b, float c, float d) {
    uint2 u;
    u.x = f2h(a, b);
    u.y = f2h(c, d);
    return u;
}

// ---------------- in-degree histogram + lookback-flag reset ----------------
__global__ void k_cnt(const int* __restrict__ dst, int E) {
    if (blockIdx.x == 0 && threadIdx.x < NBLK_SCAN)
        g_lbFlag[threadIdx.x] = 0;
    int e = blockIdx.x * blockDim.x + threadIdx.x;
    if (e < E) atomicAdd(&g_cntI[dst[e]], 1);
}

// ------- decoupled look-back scan + dinv + BN fold + resets ----------------
__global__ void __launch_bounds__(256) k_scanLB(
        const float* __restrict__ b1, const float* __restrict__ g1,
        const float* __restrict__ be1, const float* __restrict__ m1,
        const float* __restrict__ v1,
        const float* __restrict__ b2, const float* __restrict__ g2,
        const float* __restrict__ be2, const float* __restrict__ m2,
        const float* __restrict__ v2, int N, int E) {
    __shared__ int wsum[8];
    __shared__ unsigned exS;
    __shared__ int totS;
    int tid = threadIdx.x, bid = blockIdx.x;
    int lane = tid & 31, w = tid >> 5;
    int base = bid * 1024 + tid * 4;

    int v0 = 0, vv1 = 0, vv2 = 0, vv3 = 0;
    if (base + 0 < N) v0  = g_cntI[base + 0];
    if (base + 1 < N) vv1 = g_cntI[base + 1];
    if (base + 2 < N) vv2 = g_cntI[base + 2];
    if (base + 3 < N) vv3 = g_cntI[base + 3];
    int s = v0 + vv1 + vv2 + vv3;

    int inc = s;
#pragma unroll
    for (int o = 1; o < 32; o <<= 1) {
        int y = __shfl_up_sync(0xffffffff, inc, o);
        if (lane >= o) inc += y;
    }
    if (lane == 31) wsum[w] = inc;
    __syncthreads();
    if (tid == 0) {
        int run = 0;
#pragma unroll
        for (int i = 0; i < 8; i++) { int x = wsum[i]; wsum[i] = run; run += x; }
        totS = run;
        unsigned pack = (bid == 0 ? (2u << 30) : (1u << 30)) | (unsigned)run;
        atomicExch((unsigned*)&g_lbFlag[bid], pack);
    }
    __syncthreads();
    int blkEx = wsum[w] + inc - s;
    int total = totS;

    if (bid > 0) {
        if (w == 0) {
            unsigned ex = 0;
            int wnd = bid;
            for (;;) {
                int idx = wnd - 32 + lane;
                unsigned f = (1u << 30);
                if (idx >= 0) {
                    do { f = g_lbFlag[idx]; } while ((f >> 30) == 0);
                }
                unsigned isPref = __ballot_sync(0xffffffff, idx >= 0 && (f >> 30) == 2u);
                int cut = isPref ? (31 - __clz(isPref)) : -1;
                unsigned val = (lane >= cut) ? (f & 0x3FFFFFFFu) : 0u;
#pragma unroll
                for (int o = 16; o; o >>= 1) val += __shfl_down_sync(0xffffffff, val, o);
                if (lane == 0) ex += val;
                if (cut >= 0) break;
                wnd -= 32;
            }
            if (lane == 0) {
                exS = ex;
                atomicExch((unsigned*)&g_lbFlag[bid], (2u << 30) | (ex + (unsigned)total));
            }
        }
        __syncthreads();
    } else if (tid == 0) {
        exS = 0;
    }
    __syncthreads();
    unsigned ex = exS;

    int o = (int)ex + blkEx;
    if (base + 0 < N) { g_offs[base+0]=o; g_cursor[base+0]=o; g_dinv[base+0]=rsqrtf((float)v0 +1.f); g_cntI[base+0]=0; o+=v0;  }
    if (base + 1 < N) { g_offs[base+1]=o; g_cursor[base+1]=o; g_dinv[base+1]=rsqrtf((float)vv1+1.f); g_cntI[base+1]=0; o+=vv1; }
    if (base + 2 < N) { g_offs[base+2]=o; g_cursor[base+2]=o; g_dinv[base+2]=rsqrtf((float)vv2+1.f); g_cntI[base+2]=0; o+=vv2; }
    if (base + 3 < N) { g_offs[base+3]=o; g_cursor[base+3]=o; g_dinv[base+3]=rsqrtf((float)vv3+1.f); g_cntI[base+3]=0; }

    if (bid == 0 && tid == 0) g_offs[N] = E;
    if (bid == 0 && tid < D) {
        float s1 = g1[tid] * rsqrtf(v1[tid] + 1e-5f);
        g_sc1[tid] = s1;
        g_sh1[tid] = (b1[tid] - m1[tid]) * s1 + be1[tid];
        float s2 = g2[tid] * rsqrtf(v2[tid] + 1e-5f);
        g_sc2[tid] = s2;
        g_sh2[tid] = (b2[tid] - m2[tid]) * s2 + be2[tid];
    }
}

// ---------------- fill CSR (4 edges/thread for MLP) ----------------
__global__ void k_fill(const int* __restrict__ src, const int* __restrict__ dst, int E) {
    int base = (blockIdx.x * blockDim.x + threadIdx.x) * 4;
    if (base + 3 < E) {
        int d0 = dst[base + 0], d1 = dst[base + 1];
        int d2 = dst[base + 2], d3 = dst[base + 3];
        int p0 = atomicAdd(&g_cursor[d0], 1);
        int p1 = atomicAdd(&g_cursor[d1], 1);
        int p2 = atomicAdd(&g_cursor[d2], 1);
        int p3 = atomicAdd(&g_cursor[d3], 1);
        g_csrc[p0] = src[base + 0];
        g_csrc[p1] = src[base + 1];
        g_csrc[p2] = src[base + 2];
        g_csrc[p3] = src[base + 3];
    } else {
        for (int e = base; e < E; e++) {
            int d = dst[e];
            int p = atomicAdd(&g_cursor[d], 1);
            g_csrc[p] = src[e];
        }
    }
}

// ---------------- GEMM core macro ----------------
#define GEMM_ROW(ai, i)                                                           \
    acc[i][0] = fmaf(ai.w, w3.x, fmaf(ai.z, w2.x, fmaf(ai.y, w1.x, fmaf(ai.x, w0.x, acc[i][0])))); \
    acc[i][1] = fmaf(ai.w, w3.y, fmaf(ai.z, w2.y, fmaf(ai.y, w1.y, fmaf(ai.x, w0.y, acc[i][1])))); \
    acc[i][2] = fmaf(ai.w, w3.z, fmaf(ai.z, w2.z, fmaf(ai.y, w1.z, fmaf(ai.x, w0.z, acc[i][2])))); \
    acc[i][3] = fmaf(ai.w, w3.w, fmaf(ai.z, w2.w, fmaf(ai.y, w1.w, fmaf(ai.x, w0.w, acc[i][3]))));

// ------- GEMM1: C_h[N,64] = fp16(A_f32 @ W) --------------------------------
__global__ void __launch_bounds__(256) k_gemm1(const float* __restrict__ A,
                                               const float* __restrict__ W,
                                               __half* __restrict__ C, int N) {
    __shared__ __align__(16) float Ws[D * D];
    __shared__ __align__(16) float As[64 * 68];
    int tid = threadIdx.x;
    int row0 = blockIdx.x * 64;

    float4* Ws4 = (float4*)Ws;
    const float4* W4 = (const float4*)W;
#pragma unroll
    for (int i = 0; i < 4; i++) Ws4[tid + i * 256] = W4[tid + i * 256];

#pragma unroll
    for (int i = 0; i < 4; i++) {
        int idx = tid + i * 256;
        int r = idx >> 4, c4 = idx & 15;
        float4 a = make_float4(0.f, 0.f, 0.f, 0.f);
        if (row0 + r < N)
            a = __ldcs((const float4*)(A + (size_t)(row0 + r) * D) + c4);
        ((float4*)&As[r * 68])[c4] = a;
    }
    __syncthreads();

    int tx = tid & 15, ty = tid >> 4;
    float acc[4][4];
#pragma unroll
    for (int i = 0; i < 4; i++)
#pragma unroll
        for (int j = 0; j < 4; j++) acc[i][j] = 0.f;

    const float4* A0 = (const float4*)&As[(ty * 4 + 0) * 68];
    const float4* A1 = (const float4*)&As[(ty * 4 + 1) * 68];
    const float4* A2 = (const float4*)&As[(ty * 4 + 2) * 68];
    const float4* A3 = (const float4*)&As[(ty * 4 + 3) * 68];

#pragma unroll
    for (int k4 = 0; k4 < 16; k4++) {
        float4 w0 = Ws4[(4 * k4 + 0) * 16 + tx];
        float4 w1 = Ws4[(4 * k4 + 1) * 16 + tx];
        float4 w2 = Ws4[(4 * k4 + 2) * 16 + tx];
        float4 w3 = Ws4[(4 * k4 + 3) * 16 + tx];
        float4 a0 = A0[k4], a1 = A1[k4], a2 = A2[k4], a3 = A3[k4];
        GEMM_ROW(a0, 0)
        GEMM_ROW(a1, 1)
        GEMM_ROW(a2, 2)
        GEMM_ROW(a3, 3)
    }

#pragma unroll
    for (int i = 0; i < 4; i++) {
        int r = row0 + ty * 4 + i;
        if (r < N)
            ((uint2*)(C + (size_t)r * D))[tx] =
                f4_to_h4(acc[i][0], acc[i][1], acc[i][2], acc[i][3]);
    }
}

// ---- gather helpers: 32 lanes per node, lane owns 2 halves (4B) of row ----
#define G1_EDGE(sidx, wgt) do {                                                  \
    float2 f = h2f(__ldg(&hp[(size_t)(sidx) * 32 + lane]));                      \
    a0 = fmaf((wgt), f.x, a0); a1 = fmaf((wgt), f.y, a1); } while (0)

#define G2_EDGE(sidx) do {                                                       \
    float2 f = h2f(__ldg(&hp[(size_t)(sidx) * 32 + lane]));                      \
    a0 += f.x; a1 += f.y; } while (0)

// ------- layer-1 gather + BN1 + ReLU, node range [n0,n1) -------------------
__global__ void __launch_bounds__(256) k_agg1(int n0, int n1) {
    int t = blockIdx.x * blockDim.x + threadIdx.x;
    int node = n0 + (t >> 5);
    if (node >= n1) return;
    int lane = t & 31;
    const unsigned* hp = (const unsigned*)g_hH;
    float dd = g_dinv[node];
    float2 self = h2f(hp[(size_t)node * 32 + lane]);
    float a0 = dd * self.x, a1 = dd * self.y;
    int beg = g_offs[node], end = g_offs[node + 1];
    int j = beg;
    for (; j < end && (j & 3); j++) {
        int s = __ldg(&g_csrc[j]);
        float w = __ldg(&g_dinv[s]);
        G1_EDGE(s, w);
    }
    for (; j + 7 < end; j += 8) {
        int4 iA = *(const int4*)&g_csrc[j];
        int4 iB = *(const int4*)&g_csrc[j + 4];
        float wA0 = __ldg(&g_dinv[iA.x]), wA1 = __ldg(&g_dinv[iA.y]);
        float wA2 = __ldg(&g_dinv[iA.z]), wA3 = __ldg(&g_dinv[iA.w]);
        float wB0 = __ldg(&g_dinv[iB.x]), wB1 = __ldg(&g_dinv[iB.y]);
        float wB2 = __ldg(&g_dinv[iB.z]), wB3 = __ldg(&g_dinv[iB.w]);
        float2 f0 = h2f(__ldg(&hp[(size_t)iA.x * 32 + lane]));
        float2 f1 = h2f(__ldg(&hp[(size_t)iA.y * 32 + lane]));
        float2 f2 = h2f(__ldg(&hp[(size_t)iA.z * 32 + lane]));
        float2 f3 = h2f(__ldg(&hp[(size_t)iA.w * 32 + lane]));
        float2 f4 = h2f(__ldg(&hp[(size_t)iB.x * 32 + lane]));
        float2 f5 = h2f(__ldg(&hp[(size_t)iB.y * 32 + lane]));
        float2 f6 = h2f(__ldg(&hp[(size_t)iB.z * 32 + lane]));
        float2 f7 = h2f(__ldg(&hp[(size_t)iB.w * 32 + lane]));
        a0 = fmaf(wA0, f0.x, fmaf(wA1, f1.x, fmaf(wA2, f2.x, fmaf(wA3, f3.x, a0))));
        a1 = fmaf(wA0, f0.y, fmaf(wA1, f1.y, fmaf(wA2, f2.y, fmaf(wA3, f3.y, a1))));
        a0 = fmaf(wB0, f4.x, fmaf(wB1, f5.x, fmaf(wB2, f6.x, fmaf(wB3, f7.x, a0))));
        a1 = fmaf(wB0, f4.y, fmaf(wB1, f5.y, fmaf(wB2, f6.y, fmaf(wB3, f7.y, a1))));
    }
    for (; j + 3 < end; j += 4) {
        int4 iA = *(const int4*)&g_csrc[j];
        float wA0 = __ldg(&g_dinv[iA.x]), wA1 = __ldg(&g_dinv[iA.y]);
        float wA2 = __ldg(&g_dinv[iA.z]), wA3 = __ldg(&g_dinv[iA.w]);
        float2 f0 = h2f(__ldg(&hp[(size_t)iA.x * 32 + lane]));
        float2 f1 = h2f(__ldg(&hp[(size_t)iA.y * 32 + lane]));
        float2 f2 = h2f(__ldg(&hp[(size_t)iA.z * 32 + lane]));
        float2 f3 = h2f(__ldg(&hp[(size_t)iA.w * 32 + lane]));
        a0 = fmaf(wA0, f0.x, fmaf(wA1, f1.x, fmaf(wA2, f2.x, fmaf(wA3, f3.x, a0))));
        a1 = fmaf(wA0, f0.y, fmaf(wA1, f1.y, fmaf(wA2, f2.y, fmaf(wA3, f3.y, a1))));
    }
    for (; j < end; j++) {
        int s = __ldg(&g_csrc[j]);
        float w = __ldg(&g_dinv[s]);
        G1_EDGE(s, w);
    }
    int c = lane * 2;
    float y0 = fmaxf(0.f, a0 * dd * g_sc1[c + 0] + g_sh1[c + 0]);
    float y1 = fmaxf(0.f, a1 * dd * g_sc1[c + 1] + g_sh1[c + 1]);
    ((unsigned*)g_hG)[(size_t)node * 32 + lane] = f2h(y0, y1);
}

// ------- GEMM2 on row range [r0, r1): fp16 in, dinv-scaled fp16 out --------
__global__ void __launch_bounds__(256) k_gemm2(const __half* __restrict__ A,
                                               const float* __restrict__ W,
                                               __half* __restrict__ C,
                                               int r0, int r1) {
    __shared__ __align__(16) float Ws[D * D];
    __shared__ __align__(16) float As[64 * 68];
    int tid = threadIdx.x;
    int row0 = r0 + blockIdx.x * 64;

    float4* Ws4 = (float4*)Ws;
    const float4* W4 = (const float4*)W;
#pragma unroll
    for (int i = 0; i < 4; i++) Ws4[tid + i * 256] = W4[tid + i * 256];

#pragma unroll
    for (int i = 0; i < 4; i++) {
        int idx = tid + i * 256;
        int r = idx >> 4, c4 = idx & 15;
        uint2 raw = make_uint2(0u, 0u);
        if (row0 + r < r1)
            raw = __ldcs((const uint2*)(A + (size_t)(row0 + r) * D) + c4);
        float2 lo = h2f(raw.x), hi = h2f(raw.y);
        ((float4*)&As[r * 68])[c4] = make_float4(lo.x, lo.y, hi.x, hi.y);
    }
    __syncthreads();

    int tx = tid & 15, ty = tid >> 4;
    float acc[4][4];
#pragma unroll
    for (int i = 0; i < 4; i++)
#pragma unroll
        for (int j = 0; j < 4; j++) acc[i][j] = 0.f;

    const float4* A0 = (const float4*)&As[(ty * 4 + 0) * 68];
    const float4* A1 = (const float4*)&As[(ty * 4 + 1) * 68];
    const float4* A2 = (const float4*)&As[(ty * 4 + 2) * 68];
    const float4* A3 = (const float4*)&As[(ty * 4 + 3) * 68];

#pragma unroll
    for (int k4 = 0; k4 < 16; k4++) {
        float4 w0 = Ws4[(4 * k4 + 0) * 16 + tx];
        float4 w1 = Ws4[(4 * k4 + 1) * 16 + tx];
        float4 w2 = Ws4[(4 * k4 + 2) * 16 + tx];
        float4 w3 = Ws4[(4 * k4 + 3) * 16 + tx];
        float4 a0 = A0[k4], a1 = A1[k4], a2 = A2[k4], a3 = A3[k4];
        GEMM_ROW(a0, 0)
        GEMM_ROW(a1, 1)
        GEMM_ROW(a2, 2)
        GEMM_ROW(a3, 3)
    }

#pragma unroll
    for (int i = 0; i < 4; i++) {
        int r = row0 + ty * 4 + i;
        if (r < r1) {
            float sc = g_dinv[r];
            ((uint2*)(C + (size_t)r * D))[tx] =
                f4_to_h4(acc[i][0] * sc, acc[i][1] * sc,
                         acc[i][2] * sc, acc[i][3] * sc);
        }
    }
}

// ------- layer-2 gather + BN2 + ReLU + mean-pool ---------------------------
__global__ void __launch_bounds__(256) k_agg2(const int* __restrict__ batch, int N) {
    int t = blockIdx.x * blockDim.x + threadIdx.x;
    int node = t >> 5;
    if (node >= N) return;
    int lane = t & 31;
    const unsigned* hp = (const unsigned*)g_hH;
    float2 self = h2f(hp[(size_t)node * 32 + lane]);
    float a0 = self.x, a1 = self.y;
    int beg = g_offs[node], end = g_offs[node + 1];
    int j = beg;
    for (; j < end && (j & 3); j++) {
        int s = __ldg(&g_csrc[j]);
        G2_EDGE(s);
    }
    for (; j + 7 < end; j += 8) {
        int4 iA = *(const int4*)&g_csrc[j];
        int4 iB = *(const int4*)&g_csrc[j + 4];
        float2 f0 = h2f(__ldg(&hp[(size_t)iA.x * 32 + lane]));
        float2 f1 = h2f(__ldg(&hp[(size_t)iA.y * 32 + lane]));
        float2 f2 = h2f(__ldg(&hp[(size_t)iA.z * 32 + lane]));
        float2 f3 = h2f(__ldg(&hp[(size_t)iA.w * 32 + lane]));
        float2 f4 = h2f(__ldg(&hp[(size_t)iB.x * 32 + lane]));
        float2 f5 = h2f(__ldg(&hp[(size_t)iB.y * 32 + lane]));
        float2 f6 = h2f(__ldg(&hp[(size_t)iB.z * 32 + lane]));
        float2 f7 = h2f(__ldg(&hp[(size_t)iB.w * 32 + lane]));
        a0 += ((f0.x + f1.x) + (f2.x + f3.x)) + ((f4.x + f5.x) + (f6.x + f7.x));
        a1 += ((f0.y + f1.y) + (f2.y + f3.y)) + ((f4.y + f5.y) + (f6.y + f7.y));
    }
    for (; j + 3 < end; j += 4) {
        int4 iA = *(const int4*)&g_csrc[j];
        float2 f0 = h2f(__ldg(&hp[(size_t)iA.x * 32 + lane]));
        float2 f1 = h2f(__ldg(&hp[(size_t)iA.y * 32 + lane]));
        float2 f2 = h2f(__ldg(&hp[(size_t)iA.z * 32 + lane]));
        float2 f3 = h2f(__ldg(&hp[(size_t)iA.w * 32 + lane]));
        a0 += (f0.x + f1.x) + (f2.x + f3.x);
        a1 += (f0.y + f1.y) + (f2.y + f3.y);
    }
    for (; j < end; j++) {
        int s = __ldg(&g_csrc[j]);
        G2_EDGE(s);
    }
    float dd = g_dinv[node];
    int c = lane * 2;
    float y0 = fmaxf(0.f, a0 * dd * g_sc2[c + 0] + g_sh2[c + 0]);
    float y1 = fmaxf(0.f, a1 * dd * g_sc2[c + 1] + g_sh2[c + 1]);
    int g = batch[node];
    red_add_v2(&g_pooled[g * D + c], y0, y1);
    if (lane == 0) atomicAdd(&g_cnt[g], 1.0f);
}

// ------- classifier + restore pooled/cnt invariant -------------------------
__global__ void k_cls(const float* __restrict__ Wc, const float* __restrict__ bc,
                      float* __restrict__ out) {
    int t = threadIdx.x;          // 128 threads == NGRAPH*2
    int g = t >> 1, o = t & 1;
    float inv = 1.f / fmaxf(g_cnt[g], 1.f);
    float s = 0.f;
#pragma unroll
    for (int d = 0; d < D; d++) s += g_pooled[g * D + d] * Wc[d * 2 + o];
    float res = s * inv + bc[o];
    __syncthreads();
    for (int i = t; i < NGRAPH * D; i += 128) g_pooled[i] = 0.f;
    if (t < NGRAPH) g_cnt[t] = 0.f;
    out[t] = res;
}

// ---------------- host orchestration (fork/join + chunk pipeline) ----------
extern "C" void kernel_launch(void* const* d_in, const int* in_sizes, int n_in,
                              void* d_out, int out_size) {
    const float* x   = (const float*)d_in[0];
    const int*   ei  = (const int*)d_in[1];
    const int*   bat = (const int*)d_in[2];
    const float* W1  = (const float*)d_in[3];
    const float* b1  = (const float*)d_in[4];
    const float* g1  = (const float*)d_in[5];
    const float* be1 = (const float*)d_in[6];
    const float* m1  = (const float*)d_in[7];
    const float* v1  = (const float*)d_in[8];
    const float* W2  = (const float*)d_in[9];
    const float* b2  = (const float*)d_in[10];
    const float* g2  = (const float*)d_in[11];
    const float* be2 = (const float*)d_in[12];
    const float* m2  = (const float*)d_in[13];
    const float* v2  = (const float*)d_in[14];
    const float* Wc  = (const float*)d_in[15];
    const float* bc  = (const float*)d_in[16];
    float* out = (float*)d_out;

    int N = in_sizes[0] / D;
    int E = in_sizes[1] / 2;
    const int* src = ei;
    const int* dst = ei + E;

    __half *hH, *hG;
    cudaGetSymbolAddress((void**)&hH, g_hH);
    cudaGetSymbolAddress((void**)&hG, g_hG);

    int nb_edges  = (E + 255) / 256;
    int nb_fill   = (E + 1023) / 1024;
    int nb_gemm   = (N + 63) / 64;
    int nblk_scan = (N + 1023) / 1024;

    // chunk split (aligned to 64-row GEMM blocks)
    int Nh = ((N / 2) + 63) & ~63;
    if (Nh > N) Nh = N;
    int nb_agg_c0 = (int)(((long long)Nh * 32 + 255) / 256);
    int nb_agg_c1 = (int)(((long long)(N - Nh) * 32 + 255) / 256);
    int nb_g2_c0  = (Nh + 63) / 64;
    int nb_g2_c1  = (N - Nh + 63) / 64;

    static cudaStream_t sB = nullptr;
    static cudaEvent_t eFork = nullptr, eCSR = nullptr, eG1 = nullptr,
                       eA1c0 = nullptr, eA1c1 = nullptr, eG2 = nullptr;
    if (!sB) {
        cudaStreamCreateWithFlags(&sB, cudaStreamNonBlocking);
        cudaEventCreateWithFlags(&eFork, cudaEventDisableTiming);
        cudaEventCreateWithFlags(&eCSR, cudaEventDisableTiming);
        cudaEventCreateWithFlags(&eG1, cudaEventDisableTiming);
        cudaEventCreateWithFlags(&eA1c0, cudaEventDisableTiming);
        cudaEventCreateWithFlags(&eA1c1, cudaEventDisableTiming);
        cudaEventCreateWithFlags(&eG2, cudaEventDisableTiming);
    }

    // fork
    cudaEventRecord(eFork, 0);
    cudaStreamWaitEvent(sB, eFork, 0);

    // stream B: CSR chain
    k_cnt<<<nb_edges, 256, 0, sB>>>(dst, E);
    k_scanLB<<<nblk_scan, 256, 0, sB>>>(b1, g1, be1, m1, v1,
                                        b2, g2, be2, m2, v2, N, E);
    k_fill<<<nb_fill, 256, 0, sB>>>(src, dst, E);
    cudaEventRecord(eCSR, sB);

    // stream A (default): GEMM1 concurrent with CSR
    k_gemm1<<<nb_gemm, 256>>>(x, W1, hH, N);
    cudaEventRecord(eG1, 0);

    // join: agg1 needs CSR + gemm1
    cudaStreamWaitEvent(0, eCSR, 0);

    // agg1 chunk 0 on A
    k_agg1<<<nb_agg_c0, 256>>>(0, Nh);
    cudaEventRecord(eA1c0, 0);

    // agg1 chunk 1 on A
    if (Nh < N) k_agg1<<<nb_agg_c1, 256>>>(Nh, N);
    cudaEventRecord(eA1c1, 0);

    // gemm2 chunk 0 on B (needs agg1 c0 only)
    cudaStreamWaitEvent(sB, eA1c0, 0);
    k_gemm2<<<nb_g2_c0, 256, 0, sB>>>(hG, W2, hH, 0, Nh);

    // gemm2 chunk 1 on B (needs agg1 c1)
    cudaStreamWaitEvent(sB, eA1c1, 0);
    if (Nh < N) k_gemm2<<<nb_g2_c1, 256, 0, sB>>>(hG, W2, hH, Nh, N);
    cudaEventRecord(eG2, sB);

    // agg2 on A after all of gemm2
    cudaStreamWaitEvent(0, eG2, 0);
    int nb_agg_all = (int)(((long long)N * 32 + 255) / 256);
    k_agg2<<<nb_agg_all, 256>>>(bat, N);

    // classifier
    k_cls<<<1, 128>>>(Wc, bc, out);
}

// round 9
// speedup vs baseline: 1.0167x; 1.0167x over previous
#include <cuda_runtime.h>
#include <cuda_fp16.h>

#define NMAX   100000
#define EMAX   1200000
#define NGRAPH 64
#define D      64
#define NBLK_SCAN 128   // >= ceil(NMAX/1024)
#define NBAR   8

// ---------------- device scratch (no allocations allowed) ----------------
// INVARIANT at entry of every call: g_cntI==0, g_pooled==0, g_cnt==0,
// g_barCnt==0 (each is re-zeroed after last use inside the call).
// g_barGen is monotonically increasing (never reset; output-invariant).
__device__ __align__(16) __half g_hH[(size_t)NMAX * D];   // pre-agg rows (fp16)
__device__ __align__(16) __half g_hG[(size_t)NMAX * D];   // h1 rows (fp16)
__device__ float g_dinv[NMAX];
__device__ __align__(16) float g_pooled[NGRAPH * D];
__device__ float g_cnt[NGRAPH];
__device__ float g_sc1[D], g_sh1[D], g_sc2[D], g_sh2[D];

__device__ int g_cntI[NMAX];
__device__ int g_offs[NMAX + 1];
__device__ int g_cursor[NMAX];
__device__ __align__(16) int g_csrc[EMAX];
__device__ volatile unsigned g_lbFlag[NBLK_SCAN];  // status(2b)<<30 | sum

__device__ unsigned g_barCnt[NBAR];
__device__ volatile unsigned g_barGen[NBAR];

// ---------------- grid-wide barrier (all blocks resident by construction) --
__device__ __forceinline__ void gbar(int i, int NB) {
    __syncthreads();
    if (threadIdx.x == 0) {
        __threadfence();                       // release my phase's writes
        unsigned gen = g_barGen[i];
        unsigned t = atomicAdd(&g_barCnt[i], 1u);
        if (t == (unsigned)NB - 1u) {
            g_barCnt[i] = 0;                   // self-reset before release
            __threadfence();
            g_barGen[i] = gen + 1u;            // release
        } else {
            while (g_barGen[i] == gen) __nanosleep(64);
        }
        __threadfence();                       // acquire
    }
    __syncthreads();
}

__device__ __forceinline__ void red_add_v2(float* addr, float a, float b) {
    asm volatile("red.global.add.v2.f32 [%0], {%1,%2};"
                 :: "l"(addr), "f"(a), "f"(b) : "memory");
}

__device__ __forceinline__ float2 h2f(unsigned raw) {
    return __half22float2(*(__half2*)&raw);
}

__device__ __forceinline__ unsigned f2h(float a, float b) {
    __half2 p = __floats2half2_rn(a, b);
    return *(unsigned*)&p;
}

__device__ __forceinline__ uint2 f4_to_h4(float a, float b, float c, float d) {
    uint2 u;
    u.x = f2h(a, b);
    u.y = f2h(c, d);
    return u;
}

// ---------------- GEMM core macro ----------------
#define GEMM_ROW(ai, i)                                                           \
    acc[i][0] = fmaf(ai.w, w3.x, fmaf(ai.z, w2.x, fmaf(ai.y, w1.x, fmaf(ai.x, w0.x, acc[i][0])))); \
    acc[i][1] = fmaf(ai.w, w3.y, fmaf(ai.z, w2.y, fmaf(ai.y, w1.y, fmaf(ai.x, w0.y, acc[i][1])))); \
    acc[i][2] = fmaf(ai.w, w3.z, fmaf(ai.z, w2.z, fmaf(ai.y, w1.z, fmaf(ai.x, w0.z, acc[i][2])))); \
    acc[i][3] = fmaf(ai.w, w3.w, fmaf(ai.z, w2.w, fmaf(ai.y, w1.w, fmaf(ai.x, w0.w, acc[i][3]))));

// ============================================================================
// THE monolithic persistent kernel: 7 phases, 6 grid barriers, 1 launch.
// ============================================================================
__global__ void __launch_bounds__(256) k_mono(
        const float* __restrict__ x,
        const int* __restrict__ src, const int* __restrict__ dst,
        const int* __restrict__ bat,
        const float* __restrict__ W1,
        const float* __restrict__ b1, const float* __restrict__ g1,
        const float* __restrict__ be1, const float* __restrict__ m1,
        const float* __restrict__ v1,
        const float* __restrict__ W2,
        const float* __restrict__ b2, const float* __restrict__ g2,
        const float* __restrict__ be2, const float* __restrict__ m2,
        const float* __restrict__ v2,
        const float* __restrict__ Wc, const float* __restrict__ bc,
        float* __restrict__ out,
        int N, int E, int NB) {
    __shared__ __align__(16) float Ws[D * D];
    __shared__ __align__(16) float As[64 * 68];

    int tid = threadIdx.x;
    int bid = blockIdx.x;
    int gtid = bid * 256 + tid;
    int gstride = NB * 256;
    int T = (N + 63) >> 6;          // gemm tiles
    int nscan = (N + 1023) >> 10;   // scan tiles

    float4* Ws4 = (float4*)Ws;

    // ====================== P0: gemm1 (fp32->fp16) + cnt ===================
    if (bid == 0 && tid < NBLK_SCAN) g_lbFlag[tid] = 0;

    {
        const float4* W4 = (const float4*)W1;
#pragma unroll
        for (int i = 0; i < 4; i++) Ws4[tid + i * 256] = W4[tid + i * 256];
        __syncthreads();

        for (int tile = bid; tile < T; tile += NB) {
            int row0 = tile * 64;
#pragma unroll
            for (int i = 0; i < 4; i++) {
                int idx = tid + i * 256;
                int r = idx >> 4, c4 = idx & 15;
                float4 a = make_float4(0.f, 0.f, 0.f, 0.f);
                if (row0 + r < N)
                    a = __ldcs((const float4*)(x + (size_t)(row0 + r) * D) + c4);
                ((float4*)&As[r * 68])[c4] = a;
            }
            __syncthreads();

            int tx = tid & 15, ty = tid >> 4;
            float acc[4][4];
#pragma unroll
            for (int i = 0; i < 4; i++)
#pragma unroll
                for (int j = 0; j < 4; j++) acc[i][j] = 0.f;

            const float4* A0 = (const float4*)&As[(ty * 4 + 0) * 68];
            const float4* A1 = (const float4*)&As[(ty * 4 + 1) * 68];
            const float4* A2 = (const float4*)&As[(ty * 4 + 2) * 68];
            const float4* A3 = (const float4*)&As[(ty * 4 + 3) * 68];
#pragma unroll
            for (int k4 = 0; k4 < 16; k4++) {
                float4 w0 = Ws4[(4 * k4 + 0) * 16 + tx];
                float4 w1 = Ws4[(4 * k4 + 1) * 16 + tx];
                float4 w2 = Ws4[(4 * k4 + 2) * 16 + tx];
                float4 w3 = Ws4[(4 * k4 + 3) * 16 + tx];
                float4 a0 = A0[k4], a1 = A1[k4], a2 = A2[k4], a3 = A3[k4];
                GEMM_ROW(a0, 0)
                GEMM_ROW(a1, 1)
                GEMM_ROW(a2, 2)
                GEMM_ROW(a3, 3)
            }
#pragma unroll
            for (int i = 0; i < 4; i++) {
                int r = row0 + ty * 4 + i;
                if (r < N)
                    ((uint2*)(g_hH + (size_t)r * D))[tx] =
                        f4_to_h4(acc[i][0], acc[i][1], acc[i][2], acc[i][3]);
            }
            __syncthreads();
        }
    }
    // degree histogram
    for (int e = gtid; e < E; e += gstride)
        atomicAdd(&g_cntI[dst[e]], 1);

    gbar(0, NB);

    // ====================== P1: decoupled look-back scan ====================
    if (bid < nscan) {
        __shared__ int wsum[8];
        __shared__ unsigned exS;
        __shared__ int totS;
        int lane = tid & 31, w = tid >> 5;
        int base = bid * 1024 + tid * 4;

        int v0 = 0, vv1 = 0, vv2 = 0, vv3 = 0;
        if (base + 0 < N) v0  = g_cntI[base + 0];
        if (base + 1 < N) vv1 = g_cntI[base + 1];
        if (base + 2 < N) vv2 = g_cntI[base + 2];
        if (base + 3 < N) vv3 = g_cntI[base + 3];
        int s = v0 + vv1 + vv2 + vv3;

        int inc = s;
#pragma unroll
        for (int o = 1; o < 32; o <<= 1) {
            int y = __shfl_up_sync(0xffffffff, inc, o);
            if (lane >= o) inc += y;
        }
        if (lane == 31) wsum[w] = inc;
        __syncthreads();
        if (tid == 0) {
            int run = 0;
#pragma unroll
            for (int i = 0; i < 8; i++) { int xv = wsum[i]; wsum[i] = run; run += xv; }
            totS = run;
            unsigned pack = (bid == 0 ? (2u << 30) : (1u << 30)) | (unsigned)run;
            atomicExch((unsigned*)&g_lbFlag[bid], pack);
        }
        __syncthreads();
        int blkEx = wsum[w] + inc - s;
        int total = totS;

        if (bid > 0) {
            if (w == 0) {
                unsigned ex = 0;
                int wnd = bid;
                for (;;) {
                    int idx = wnd - 32 + lane;
                    unsigned f = (1u << 30);
                    if (idx >= 0) {
                        do { f = g_lbFlag[idx]; } while ((f >> 30) == 0);
                    }
                    unsigned isPref = __ballot_sync(0xffffffff, idx >= 0 && (f >> 30) == 2u);
                    int cut = isPref ? (31 - __clz(isPref)) : -1;
                    unsigned val = (lane >= cut) ? (f & 0x3FFFFFFFu) : 0u;
#pragma unroll
                    for (int o = 16; o; o >>= 1) val += __shfl_down_sync(0xffffffff, val, o);
                    if (lane == 0) ex += val;
                    if (cut >= 0) break;
                    wnd -= 32;
                }
                if (lane == 0) {
                    exS = ex;
                    atomicExch((unsigned*)&g_lbFlag[bid], (2u << 30) | (ex + (unsigned)total));
                }
            }
            __syncthreads();
        } else if (tid == 0) {
            exS = 0;
        }
        __syncthreads();
        unsigned ex = exS;

        int o = (int)ex + blkEx;
        if (base + 0 < N) { g_offs[base+0]=o; g_cursor[base+0]=o; g_dinv[base+0]=rsqrtf((float)v0 +1.f); g_cntI[base+0]=0; o+=v0;  }
        if (base + 1 < N) { g_offs[base+1]=o; g_cursor[base+1]=o; g_dinv[base+1]=rsqrtf((float)vv1+1.f); g_cntI[base+1]=0; o+=vv1; }
        if (base + 2 < N) { g_offs[base+2]=o; g_cursor[base+2]=o; g_dinv[base+2]=rsqrtf((float)vv2+1.f); g_cntI[base+2]=0; o+=vv2; }
        if (base + 3 < N) { g_offs[base+3]=o; g_cursor[base+3]=o; g_dinv[base+3]=rsqrtf((float)vv3+1.f); g_cntI[base+3]=0; }

        if (bid == 0 && tid == 0) g_offs[N] = E;
        if (bid == 0 && tid < D) {
            float s1 = g1[tid] * rsqrtf(v1[tid] + 1e-5f);
            g_sc1[tid] = s1;
            g_sh1[tid] = (b1[tid] - m1[tid]) * s1 + be1[tid];
            float s2 = g2[tid] * rsqrtf(v2[tid] + 1e-5f);
            g_sc2[tid] = s2;
            g_sh2[tid] = (b2[tid] - m2[tid]) * s2 + be2[tid];
        }
    }

    gbar(1, NB);

    // ====================== P2: CSR fill ====================================
    for (int e = gtid; e < E; e += gstride) {
        int d = dst[e];
        int p = atomicAdd(&g_cursor[d], 1);
        g_csrc[p] = src[e];
    }

    gbar(2, NB);

    // ====================== P3: agg1 + BN1 + ReLU ===========================
    {
        int lane = tid & 31;
        int gwarp = bid * 8 + (tid >> 5);
        int wstride = NB * 8;
        const unsigned* hp = (const unsigned*)g_hH;
        for (int node = gwarp; node < N; node += wstride) {
            float dd = g_dinv[node];
            float2 self = h2f(hp[(size_t)node * 32 + lane]);
            float a0 = dd * self.x, a1 = dd * self.y;
            int beg = g_offs[node], end = g_offs[node + 1];
            int j = beg;
            for (; j < end && (j & 3); j++) {
                int s = __ldg(&g_csrc[j]);
                float w = __ldg(&g_dinv[s]);
                float2 f = h2f(__ldg(&hp[(size_t)s * 32 + lane]));
                a0 = fmaf(w, f.x, a0); a1 = fmaf(w, f.y, a1);
            }
            for (; j + 7 < end; j += 8) {
                int4 iA = *(const int4*)&g_csrc[j];
                int4 iB = *(const int4*)&g_csrc[j + 4];
                float wA0 = __ldg(&g_dinv[iA.x]), wA1 = __ldg(&g_dinv[iA.y]);
                float wA2 = __ldg(&g_dinv[iA.z]), wA3 = __ldg(&g_dinv[iA.w]);
                float wB0 = __ldg(&g_dinv[iB.x]), wB1 = __ldg(&g_dinv[iB.y]);
                float wB2 = __ldg(&g_dinv[iB.z]), wB3 = __ldg(&g_dinv[iB.w]);
                float2 f0 = h2f(__ldg(&hp[(size_t)iA.x * 32 + lane]));
                float2 f1 = h2f(__ldg(&hp[(size_t)iA.y * 32 + lane]));
                float2 f2 = h2f(__ldg(&hp[(size_t)iA.z * 32 + lane]));
                float2 f3 = h2f(__ldg(&hp[(size_t)iA.w * 32 + lane]));
                float2 f4 = h2f(__ldg(&hp[(size_t)iB.x * 32 + lane]));
                float2 f5 = h2f(__ldg(&hp[(size_t)iB.y * 32 + lane]));
                float2 f6 = h2f(__ldg(&hp[(size_t)iB.z * 32 + lane]));
                float2 f7 = h2f(__ldg(&hp[(size_t)iB.w * 32 + lane]));
                a0 = fmaf(wA0, f0.x, fmaf(wA1, f1.x, fmaf(wA2, f2.x, fmaf(wA3, f3.x, a0))));
                a1 = fmaf(wA0, f0.y, fmaf(wA1, f1.y, fmaf(wA2, f2.y, fmaf(wA3, f3.y, a1))));
                a0 = fmaf(wB0, f4.x, fmaf(wB1, f5.x, fmaf(wB2, f6.x, fmaf(wB3, f7.x, a0))));
                a1 = fmaf(wB0, f4.y, fmaf(wB1, f5.y, fmaf(wB2, f6.y, fmaf(wB3, f7.y, a1))));
            }
            for (; j + 3 < end; j += 4) {
                int4 iA = *(const int4*)&g_csrc[j];
                float wA0 = __ldg(&g_dinv[iA.x]), wA1 = __ldg(&g_dinv[iA.y]);
                float wA2 = __ldg(&g_dinv[iA.z]), wA3 = __ldg(&g_dinv[iA.w]);
                float2 f0 = h2f(__ldg(&hp[(size_t)iA.x * 32 + lane]));
                float2 f1 = h2f(__ldg(&hp[(size_t)iA.y * 32 + lane]));
                float2 f2 = h2f(__ldg(&hp[(size_t)iA.z * 32 + lane]));
                float2 f3 = h2f(__ldg(&hp[(size_t)iA.w * 32 + lane]));
                a0 = fmaf(wA0, f0.x, fmaf(wA1, f1.x, fmaf(wA2, f2.x, fmaf(wA3, f3.x, a0))));
                a1 = fmaf(wA0, f0.y, fmaf(wA1, f1.y, fmaf(wA2, f2.y, fmaf(wA3, f3.y, a1))));
            }
            for (; j < end; j++) {
                int s = __ldg(&g_csrc[j]);
                float w = __ldg(&g_dinv[s]);
                float2 f = h2f(__ldg(&hp[(size_t)s * 32 + lane]));
                a0 = fmaf(w, f.x, a0); a1 = fmaf(w, f.y, a1);
            }
            int c = lane * 2;
            float y0 = fmaxf(0.f, a0 * dd * g_sc1[c + 0] + g_sh1[c + 0]);
            float y1 = fmaxf(0.f, a1 * dd * g_sc1[c + 1] + g_sh1[c + 1]);
            ((unsigned*)g_hG)[(size_t)node * 32 + lane] = f2h(y0, y1);
        }
    }

    gbar(3, NB);

    // ====================== P4: gemm2 (fp16 -> dinv-scaled fp16) ============
    {
        const float4* W4 = (const float4*)W2;
#pragma unroll
        for (int i = 0; i < 4; i++) Ws4[tid + i * 256] = W4[tid + i * 256];
        __syncthreads();

        for (int tile = bid; tile < T; tile += NB) {
            int row0 = tile * 64;
#pragma unroll
            for (int i = 0; i < 4; i++) {
                int idx = tid + i * 256;
                int r = idx >> 4, c4 = idx & 15;
                uint2 raw = make_uint2(0u, 0u);
                if (row0 + r < N)
                    raw = __ldcs((const uint2*)(g_hG + (size_t)(row0 + r) * D) + c4);
                float2 lo = h2f(raw.x), hi = h2f(raw.y);
                ((float4*)&As[r * 68])[c4] = make_float4(lo.x, lo.y, hi.x, hi.y);
            }
            __syncthreads();

            int tx = tid & 15, ty = tid >> 4;
            float acc[4][4];
#pragma unroll
            for (int i = 0; i < 4; i++)
#pragma unroll
                for (int j = 0; j < 4; j++) acc[i][j] = 0.f;

            const float4* A0 = (const float4*)&As[(ty * 4 + 0) * 68];
            const float4* A1 = (const float4*)&As[(ty * 4 + 1) * 68];
            const float4* A2 = (const float4*)&As[(ty * 4 + 2) * 68];
            const float4* A3 = (const float4*)&As[(ty * 4 + 3) * 68];
#pragma unroll
            for (int k4 = 0; k4 < 16; k4++) {
                float4 w0 = Ws4[(4 * k4 + 0) * 16 + tx];
                float4 w1 = Ws4[(4 * k4 + 1) * 16 + tx];
                float4 w2 = Ws4[(4 * k4 + 2) * 16 + tx];
                float4 w3 = Ws4[(4 * k4 + 3) * 16 + tx];
                float4 a0 = A0[k4], a1 = A1[k4], a2 = A2[k4], a3 = A3[k4];
                GEMM_ROW(a0, 0)
                GEMM_ROW(a1, 1)
                GEMM_ROW(a2, 2)
                GEMM_ROW(a3, 3)
            }
#pragma unroll
            for (int i = 0; i < 4; i++) {
                int r = row0 + ty * 4 + i;
                if (r < N) {
                    float sc = g_dinv[r];
                    ((uint2*)(g_hH + (size_t)r * D))[tx] =
                        f4_to_h4(acc[i][0] * sc, acc[i][1] * sc,
                                 acc[i][2] * sc, acc[i][3] * sc);
                }
            }
            __syncthreads();
        }
    }

    gbar(4, NB);

    // ====================== P5: agg2 + BN2 + ReLU + mean-pool ===============
    {
        int lane = tid & 31;
        int gwarp = bid * 8 + (tid >> 5);
        int wstride = NB * 8;
        const unsigned* hp = (const unsigned*)g_hH;
        for (int node = gwarp; node < N; node += wstride) {
            float2 self = h2f(hp[(size_t)node * 32 + lane]);
            float a0 = self.x, a1 = self.y;
            int beg = g_offs[node], end = g_offs[node + 1];
            int j = beg;
            for (; j < end && (j & 3); j++) {
                int s = __ldg(&g_csrc[j]);
                float2 f = h2f(__ldg(&hp[(size_t)s * 32 + lane]));
                a0 += f.x; a1 += f.y;
            }
            for (; j + 7 < end; j += 8) {
                int4 iA = *(const int4*)&g_csrc[j];
                int4 iB = *(const int4*)&g_csrc[j + 4];
                float2 f0 = h2f(__ldg(&hp[(size_t)iA.x * 32 + lane]));
                float2 f1 = h2f(__ldg(&hp[(size_t)iA.y * 32 + lane]));
                float2 f2 = h2f(__ldg(&hp[(size_t)iA.z * 32 + lane]));
                float2 f3 = h2f(__ldg(&hp[(size_t)iA.w * 32 + lane]));
                float2 f4 = h2f(__ldg(&hp[(size_t)iB.x * 32 + lane]));
                float2 f5 = h2f(__ldg(&hp[(size_t)iB.y * 32 + lane]));
                float2 f6 = h2f(__ldg(&hp[(size_t)iB.z * 32 + lane]));
                float2 f7 = h2f(__ldg(&hp[(size_t)iB.w * 32 + lane]));
                a0 += ((f0.x + f1.x) + (f2.x + f3.x)) + ((f4.x + f5.x) + (f6.x + f7.x));
                a1 += ((f0.y + f1.y) + (f2.y + f3.y)) + ((f4.y + f5.y) + (f6.y + f7.y));
            }
            for (; j + 3 < end; j += 4) {
                int4 iA = *(const int4*)&g_csrc[j];
                float2 f0 = h2f(__ldg(&hp[(size_t)iA.x * 32 + lane]));
                float2 f1 = h2f(__ldg(&hp[(size_t)iA.y * 32 + lane]));
                float2 f2 = h2f(__ldg(&hp[(size_t)iA.z * 32 + lane]));
                float2 f3 = h2f(__ldg(&hp[(size_t)iA.w * 32 + lane]));
                a0 += (f0.x + f1.x) + (f2.x + f3.x);
                a1 += (f0.y + f1.y) + (f2.y + f3.y);
            }
            for (; j < end; j++) {
                int s = __ldg(&g_csrc[j]);
                float2 f = h2f(__ldg(&hp[(size_t)s * 32 + lane]));
                a0 += f.x; a1 += f.y;
            }
            float dd = g_dinv[node];
            int c = lane * 2;
            float y0 = fmaxf(0.f, a0 * dd * g_sc2[c + 0] + g_sh2[c + 0]);
            float y1 = fmaxf(0.f, a1 * dd * g_sc2[c + 1] + g_sh2[c + 1]);
            int g = bat[node];
            red_add_v2(&g_pooled[g * D + c], y0, y1);
            if (lane == 0) atomicAdd(&g_cnt[g], 1.0f);
        }
    }

    gbar(5, NB);

    // ====================== P6: classifier + invariant restore ==============
    if (bid == 0) {
        if (tid < NGRAPH * 2) {
            int g = tid >> 1, o = tid & 1;
            float inv = 1.f / fmaxf(g_cnt[g], 1.f);
            float s = 0.f;
#pragma unroll
            for (int d = 0; d < D; d++) s += g_pooled[g * D + d] * Wc[d * 2 + o];
            out[tid] = s * inv + bc[o];
        }
        __syncthreads();
        for (int i = tid; i < NGRAPH * D; i += 256) g_pooled[i] = 0.f;
        if (tid < NGRAPH) g_cnt[tid] = 0.f;
    }
}

// ---------------- host orchestration: ONE launch ----------------
extern "C" void kernel_launch(void* const* d_in, const int* in_sizes, int n_in,
                              void* d_out, int out_size) {
    const float* x   = (const float*)d_in[0];
    const int*   ei  = (const int*)d_in[1];
    const int*   bat = (const int*)d_in[2];
    const float* W1  = (const float*)d_in[3];
    const float* b1  = (const float*)d_in[4];
    const float* g1  = (const float*)d_in[5];
    const float* be1 = (const float*)d_in[6];
    const float* m1  = (const float*)d_in[7];
    const float* v1  = (const float*)d_in[8];
    const float* W2  = (const float*)d_in[9];
    const float* b2  = (const float*)d_in[10];
    const float* g2  = (const float*)d_in[11];
    const float* be2 = (const float*)d_in[12];
    const float* m2  = (const float*)d_in[13];
    const float* v2  = (const float*)d_in[14];
    const float* Wc  = (const float*)d_in[15];
    const float* bc  = (const float*)d_in[16];
    float* out = (float*)d_out;

    int N = in_sizes[0] / D;
    int E = in_sizes[1] / 2;
    const int* src = ei;
    const int* dst = ei + E;

    // size grid so all blocks are co-resident (barrier-safe by construction)
    static int NB = 0;
    if (NB == 0) {
        int dev = 0, nsm = 0, bpm = 0;
        cudaGetDevice(&dev);
        cudaDeviceGetAttribute(&nsm, cudaDevAttrMultiProcessorCount, dev);
        cudaOccupancyMaxActiveBlocksPerMultiprocessor(&bpm, k_mono, 256, 0);
        if (bpm < 1) bpm = 1;
        NB = nsm * bpm;
        if (NB < NBLK_SCAN) NB = NBLK_SCAN;   // scan needs all tiles resident
    }

    k_mono<<<NB, 256>>>(x, src, dst, bat, W1, b1, g1, be1, m1, v1,
                        W2, b2, g2, be2, m2, v2, Wc, bc, out, N, E, NB);
}

// round 10
// speedup vs baseline: 1.0168x; 1.0001x over previous
#include <cuda_runtime.h>
#include <cuda_fp16.h>

#define NMAX   100000
#define EMAX   1200000
#define NGRAPH 64
#define D      64
#define NBLK_SCAN 128   // >= ceil(NMAX/1024)

// ---------------- device scratch (no allocations allowed) ----------------
// INVARIANT at entry of every call: g_cntI==0, g_pooled==0, g_cnt==0, g_done==0.
__device__ __align__(16) __half g_hH[(size_t)NMAX * D];   // pre-agg rows (fp16)
__device__ __align__(16) __half g_hG[(size_t)NMAX * D];   // h1 rows (fp16)
__device__ float g_dinv[NMAX];
__device__ __align__(16) float g_pooled[NGRAPH * D];
__device__ float g_cnt[NGRAPH];
__device__ float g_sc1[D], g_sh1[D], g_sc2[D], g_sh2[D];

__device__ int g_cntI[NMAX];
__device__ int g_offs[NMAX + 1];
__device__ int g_cursor[NMAX];
__device__ __align__(16) int g_csrc[EMAX];
__device__ volatile unsigned g_lbFlag[NBLK_SCAN];  // status(2b)<<30 | sum
__device__ unsigned g_done;

__device__ __forceinline__ void red_add_v2(float* addr, float a, float b) {
    asm volatile("red.global.add.v2.f32 [%0], {%1,%2};"
                 :: "l"(addr), "f"(a), "f"(b) : "memory");
}

__device__ __forceinline__ float2 h2f(unsigned raw) {
    return __half22float2(*(__half2*)&raw);
}

__device__ __forceinline__ unsigned f2h(float a, float b) {
    __half2 p = __floats2half2_rn(a, b);
    return *(unsigned*)&p;
}

__device__ __forceinline__ uint2 f4_to_h4(float a, float b, float c, float d) {
    uint2 u;
    u.x = f2h(a, b);
    u.y = f2h(c, d);
    return u;
}

__device__ __forceinline__ void mma16816(float* c, unsigned a0, unsigned a1,
                                         unsigned a2, unsigned a3,
                                         unsigned b0, unsigned b1) {
    asm volatile(
        "mma.sync.aligned.m16n8k16.row.col.f32.f16.f16.f32 "
        "{%0,%1,%2,%3}, {%4,%5,%6,%7}, {%8,%9}, {%0,%1,%2,%3};"
        : "+f"(c[0]), "+f"(c[1]), "+f"(c[2]), "+f"(c[3])
        : "r"(a0), "r"(a1), "r"(a2), "r"(a3), "r"(b0), "r"(b1));
}

// ---------------- in-degree histogram + lookback-flag reset ----------------
__global__ void k_cnt(const int* __restrict__ dst, int E) {
    if (blockIdx.x == 0 && threadIdx.x < NBLK_SCAN)
        g_lbFlag[threadIdx.x] = 0;
    int e = blockIdx.x * blockDim.x + threadIdx.x;
    if (e < E) atomicAdd(&g_cntI[dst[e]], 1);
}

// ------- decoupled look-back scan + dinv + BN fold + resets ----------------
__global__ void __launch_bounds__(256) k_scanLB(
        const float* __restrict__ b1, const float* __restrict__ g1,
        const float* __restrict__ be1, const float* __restrict__ m1,
        const float* __restrict__ v1,
        const float* __restrict__ b2, const float* __restrict__ g2,
        const float* __restrict__ be2, const float* __restrict__ m2,
        const float* __restrict__ v2, int N, int E) {
    __shared__ int wsum[8];
    __shared__ unsigned exS;
    __shared__ int totS;
    int tid = threadIdx.x, bid = blockIdx.x;
    int lane = tid & 31, w = tid >> 5;
    int base = bid * 1024 + tid * 4;

    int v0 = 0, vv1 = 0, vv2 = 0, vv3 = 0;
    if (base + 0 < N) v0  = g_cntI[base + 0];
    if (base + 1 < N) vv1 = g_cntI[base + 1];
    if (base + 2 < N) vv2 = g_cntI[base + 2];
    if (base + 3 < N) vv3 = g_cntI[base + 3];
    int s = v0 + vv1 + vv2 + vv3;

    int inc = s;
#pragma unroll
    for (int o = 1; o < 32; o <<= 1) {
        int y = __shfl_up_sync(0xffffffff, inc, o);
        if (lane >= o) inc += y;
    }
    if (lane == 31) wsum[w] = inc;
    __syncthreads();
    if (tid == 0) {
        int run = 0;
#pragma unroll
        for (int i = 0; i < 8; i++) { int xv = wsum[i]; wsum[i] = run; run += xv; }
        totS = run;
        unsigned pack = (bid == 0 ? (2u << 30) : (1u << 30)) | (unsigned)run;
        atomicExch((unsigned*)&g_lbFlag[bid], pack);
    }
    __syncthreads();
    int blkEx = wsum[w] + inc - s;
    int total = totS;

    if (bid > 0) {
        if (w == 0) {
            unsigned ex = 0;
            int wnd = bid;
            for (;;) {
                int idx = wnd - 32 + lane;
                unsigned f = (1u << 30);
                if (idx >= 0) {
                    do { f = g_lbFlag[idx]; } while ((f >> 30) == 0);
                }
                unsigned isPref = __ballot_sync(0xffffffff, idx >= 0 && (f >> 30) == 2u);
                int cut = isPref ? (31 - __clz(isPref)) : -1;
                unsigned val = (lane >= cut) ? (f & 0x3FFFFFFFu) : 0u;
#pragma unroll
                for (int o = 16; o; o >>= 1) val += __shfl_down_sync(0xffffffff, val, o);
                if (lane == 0) ex += val;
                if (cut >= 0) break;
                wnd -= 32;
            }
            if (lane == 0) {
                exS = ex;
                atomicExch((unsigned*)&g_lbFlag[bid], (2u << 30) | (ex + (unsigned)total));
            }
        }
        __syncthreads();
    } else if (tid == 0) {
        exS = 0;
    }
    __syncthreads();
    unsigned ex = exS;

    int o = (int)ex + blkEx;
    if (base + 0 < N) { g_offs[base+0]=o; g_cursor[base+0]=o; g_dinv[base+0]=rsqrtf((float)v0 +1.f); g_cntI[base+0]=0; o+=v0;  }
    if (base + 1 < N) { g_offs[base+1]=o; g_cursor[base+1]=o; g_dinv[base+1]=rsqrtf((float)vv1+1.f); g_cntI[base+1]=0; o+=vv1; }
    if (base + 2 < N) { g_offs[base+2]=o; g_cursor[base+2]=o; g_dinv[base+2]=rsqrtf((float)vv2+1.f); g_cntI[base+2]=0; o+=vv2; }
    if (base + 3 < N) { g_offs[base+3]=o; g_cursor[base+3]=o; g_dinv[base+3]=rsqrtf((float)vv3+1.f); g_cntI[base+3]=0; }

    if (bid == 0 && tid == 0) g_offs[N] = E;
    if (bid == 0 && tid < D) {
        float s1 = g1[tid] * rsqrtf(v1[tid] + 1e-5f);
        g_sc1[tid] = s1;
        g_sh1[tid] = (b1[tid] - m1[tid]) * s1 + be1[tid];
        float s2 = g2[tid] * rsqrtf(v2[tid] + 1e-5f);
        g_sc2[tid] = s2;
        g_sh2[tid] = (b2[tid] - m2[tid]) * s2 + be2[tid];
    }
}

// ---------------- fill CSR ----------------
__global__ void k_fill(const int* __restrict__ src, const int* __restrict__ dst, int E) {
    int e = blockIdx.x * blockDim.x + threadIdx.x;
    if (e < E) {
        int d = dst[e];
        int p = atomicAdd(&g_cursor[d], 1);
        g_csrc[p] = src[e];
    }
}

// ---------------- GEMM1 core macro ----------------
#define GEMM_ROW(ai, i)                                                           \
    acc[i][0] = fmaf(ai.w, w3.x, fmaf(ai.z, w2.x, fmaf(ai.y, w1.x, fmaf(ai.x, w0.x, acc[i][0])))); \
    acc[i][1] = fmaf(ai.w, w3.y, fmaf(ai.z, w2.y, fmaf(ai.y, w1.y, fmaf(ai.x, w0.y, acc[i][1])))); \
    acc[i][2] = fmaf(ai.w, w3.z, fmaf(ai.z, w2.z, fmaf(ai.y, w1.z, fmaf(ai.x, w0.z, acc[i][2])))); \
    acc[i][3] = fmaf(ai.w, w3.w, fmaf(ai.z, w2.w, fmaf(ai.y, w1.w, fmaf(ai.x, w0.w, acc[i][3]))));

// ------- GEMM1: C_h[N,64] = fp16(A_f32 @ W1) (unscaled; runs ∥ CSR chain) --
__global__ void __launch_bounds__(256) k_gemm1(const float* __restrict__ A,
                                               const float* __restrict__ W,
                                               __half* __restrict__ C, int N) {
    __shared__ __align__(16) float Ws[D * D];
    __shared__ __align__(16) float As[64 * 68];
    int tid = threadIdx.x;
    int row0 = blockIdx.x * 64;

    float4* Ws4 = (float4*)Ws;
    const float4* W4 = (const float4*)W;
#pragma unroll
    for (int i = 0; i < 4; i++) Ws4[tid + i * 256] = W4[tid + i * 256];

#pragma unroll
    for (int i = 0; i < 4; i++) {
        int idx = tid + i * 256;
        int r = idx >> 4, c4 = idx & 15;
        float4 a = make_float4(0.f, 0.f, 0.f, 0.f);
        if (row0 + r < N)
            a = __ldcs((const float4*)(A + (size_t)(row0 + r) * D) + c4);
        ((float4*)&As[r * 68])[c4] = a;
    }
    __syncthreads();

    int tx = tid & 15, ty = tid >> 4;
    float acc[4][4];
#pragma unroll
    for (int i = 0; i < 4; i++)
#pragma unroll
        for (int j = 0; j < 4; j++) acc[i][j] = 0.f;

    const float4* A0 = (const float4*)&As[(ty * 4 + 0) * 68];
    const float4* A1 = (const float4*)&As[(ty * 4 + 1) * 68];
    const float4* A2 = (const float4*)&As[(ty * 4 + 2) * 68];
    const float4* A3 = (const float4*)&As[(ty * 4 + 3) * 68];

#pragma unroll
    for (int k4 = 0; k4 < 16; k4++) {
        float4 w0 = Ws4[(4 * k4 + 0) * 16 + tx];
        float4 w1 = Ws4[(4 * k4 + 1) * 16 + tx];
        float4 w2 = Ws4[(4 * k4 + 2) * 16 + tx];
        float4 w3 = Ws4[(4 * k4 + 3) * 16 + tx];
        float4 a0 = A0[k4], a1 = A1[k4], a2 = A2[k4], a3 = A3[k4];
        GEMM_ROW(a0, 0)
        GEMM_ROW(a1, 1)
        GEMM_ROW(a2, 2)
        GEMM_ROW(a3, 3)
    }

#pragma unroll
    for (int i = 0; i < 4; i++) {
        int r = row0 + ty * 4 + i;
        if (r < N)
            ((uint2*)(C + (size_t)r * D))[tx] =
                f4_to_h4(acc[i][0], acc[i][1], acc[i][2], acc[i][3]);
    }
}

// ------- prescale: hH[i] *= dinv[node]  (in place; needs dinv ready) -------
__global__ void k_scale(int N) {
    int t = blockIdx.x * blockDim.x + threadIdx.x;
    if (t >= N * 32) return;
    unsigned* hp = (unsigned*)g_hH;
    float dd = g_dinv[t >> 5];
    float2 f = h2f(hp[t]);
    hp[t] = f2h(f.x * dd, f.y * dd);
}

// ------- agg1: plain-sum gather of prescaled rows + BN1 + ReLU -------------
__global__ void __launch_bounds__(256) k_agg1(int N) {
    int t = blockIdx.x * blockDim.x + threadIdx.x;
    int node = t >> 5;
    if (node >= N) return;
    int lane = t & 31;
    const unsigned* hp = (const unsigned*)g_hH;
    float2 self = h2f(hp[(size_t)node * 32 + lane]);   // already *dinv[node]
    float a0 = self.x, a1 = self.y;
    int beg = g_offs[node], end = g_offs[node + 1];
    int j = beg;
    for (; j < end && (j & 3); j++) {
        int s = __ldg(&g_csrc[j]);
        float2 f = h2f(__ldg(&hp[(size_t)s * 32 + lane]));
        a0 += f.x; a1 += f.y;
    }
    for (; j + 7 < end; j += 8) {
        int4 iA = *(const int4*)&g_csrc[j];
        int4 iB = *(const int4*)&g_csrc[j + 4];
        float2 f0 = h2f(__ldg(&hp[(size_t)iA.x * 32 + lane]));
        float2 f1 = h2f(__ldg(&hp[(size_t)iA.y * 32 + lane]));
        float2 f2 = h2f(__ldg(&hp[(size_t)iA.z * 32 + lane]));
        float2 f3 = h2f(__ldg(&hp[(size_t)iA.w * 32 + lane]));
        float2 f4 = h2f(__ldg(&hp[(size_t)iB.x * 32 + lane]));
        float2 f5 = h2f(__ldg(&hp[(size_t)iB.y * 32 + lane]));
        float2 f6 = h2f(__ldg(&hp[(size_t)iB.z * 32 + lane]));
        float2 f7 = h2f(__ldg(&hp[(size_t)iB.w * 32 + lane]));
        a0 += ((f0.x + f1.x) + (f2.x + f3.x)) + ((f4.x + f5.x) + (f6.x + f7.x));
        a1 += ((f0.y + f1.y) + (f2.y + f3.y)) + ((f4.y + f5.y) + (f6.y + f7.y));
    }
    for (; j + 3 < end; j += 4) {
        int4 iA = *(const int4*)&g_csrc[j];
        float2 f0 = h2f(__ldg(&hp[(size_t)iA.x * 32 + lane]));
        float2 f1 = h2f(__ldg(&hp[(size_t)iA.y * 32 + lane]));
        float2 f2 = h2f(__ldg(&hp[(size_t)iA.z * 32 + lane]));
        float2 f3 = h2f(__ldg(&hp[(size_t)iA.w * 32 + lane]));
        a0 += (f0.x + f1.x) + (f2.x + f3.x);
        a1 += (f0.y + f1.y) + (f2.y + f3.y);
    }
    for (; j < end; j++) {
        int s = __ldg(&g_csrc[j]);
        float2 f = h2f(__ldg(&hp[(size_t)s * 32 + lane]));
        a0 += f.x; a1 += f.y;
    }
    float dd = g_dinv[node];
    int c = lane * 2;
    float y0 = fmaxf(0.f, a0 * dd * g_sc1[c + 0] + g_sh1[c + 0]);
    float y1 = fmaxf(0.f, a1 * dd * g_sc1[c + 1] + g_sh1[c + 1]);
    ((unsigned*)g_hG)[(size_t)node * 32 + lane] = f2h(y0, y1);
}

// ------- GEMM2 tensor-core: hH = fp16((hG @ W2) * dinv), W2 split hi+res ---
__global__ void __launch_bounds__(256) k_gemm2tc(const __half* __restrict__ A,
                                                 const float* __restrict__ W,
                                                 __half* __restrict__ C, int N) {
    __shared__ __align__(16) __half As[128 * 72];
    __shared__ __align__(16) __half Wh[64 * 72];
    __shared__ __align__(16) __half Wr[64 * 72];
    int tid = threadIdx.x;
    int warp = tid >> 5, lane = tid & 31;
    int row0 = blockIdx.x * 128;

    // W2 -> fp16 hi + fp16 residual, transposed [n][k]
#pragma unroll
    for (int i = 0; i < 16; i++) {
        int idx = tid + i * 256;
        int k = idx >> 6, n = idx & 63;
        float w = W[k * 64 + n];
        __half wh = __float2half_rn(w);
        Wh[n * 72 + k] = wh;
        Wr[n * 72 + k] = __float2half_rn(w - __half2float(wh));
    }

    // A tile: 128 rows x 64 halves, row stride 72 halves
#pragma unroll
    for (int i = 0; i < 4; i++) {
        int idx = tid + i * 256;
        int r = idx >> 3, c8 = idx & 7;
        uint4 raw = make_uint4(0u, 0u, 0u, 0u);
        if (row0 + r < N)
            raw = __ldcs((const uint4*)(A + (size_t)(row0 + r) * D) + c8);
        *(uint4*)&As[r * 72 + c8 * 8] = raw;
    }
    __syncthreads();

    int g = lane >> 2, tg = lane & 3;
    int rbase = warp * 16;
    float acc[8][4];
#pragma unroll
    for (int nt = 0; nt < 8; nt++)
#pragma unroll
        for (int i = 0; i < 4; i++) acc[nt][i] = 0.f;

#pragma unroll
    for (int k0 = 0; k0 < 64; k0 += 16) {
        unsigned ra0 = *(const unsigned*)&As[(rbase + g) * 72 + k0 + tg * 2];
        unsigned ra1 = *(const unsigned*)&As[(rbase + g + 8) * 72 + k0 + tg * 2];
        unsigned ra2 = *(const unsigned*)&As[(rbase + g) * 72 + k0 + tg * 2 + 8];
        unsigned ra3 = *(const unsigned*)&As[(rbase + g + 8) * 72 + k0 + tg * 2 + 8];
#pragma unroll
        for (int nt = 0; nt < 8; nt++) {
            int nrow = (nt * 8 + g) * 72 + k0 + tg * 2;
            unsigned bh0 = *(const unsigned*)&Wh[nrow];
            unsigned bh1 = *(const unsigned*)&Wh[nrow + 8];
            mma16816(acc[nt], ra0, ra1, ra2, ra3, bh0, bh1);
            unsigned br0 = *(const unsigned*)&Wr[nrow];
            unsigned br1 = *(const unsigned*)&Wr[nrow + 8];
            mma16816(acc[nt], ra0, ra1, ra2, ra3, br0, br1);
        }
    }

    int r0g = row0 + rbase + g;
    int r1g = r0g + 8;
    float d0 = (r0g < N) ? g_dinv[r0g] : 0.f;
    float d1 = (r1g < N) ? g_dinv[r1g] : 0.f;
#pragma unroll
    for (int nt = 0; nt < 8; nt++) {
        int n = nt * 8 + tg * 2;
        if (r0g < N)
            *(unsigned*)(C + (size_t)r0g * D + n) = f2h(acc[nt][0] * d0, acc[nt][1] * d0);
        if (r1g < N)
            *(unsigned*)(C + (size_t)r1g * D + n) = f2h(acc[nt][2] * d1, acc[nt][3] * d1);
    }
}

// ------- agg2 + BN2 + ReLU + mean-pool + (last block) classifier -----------
__global__ void __launch_bounds__(256) k_agg2cls(const int* __restrict__ batch,
                                                 const float* __restrict__ Wc,
                                                 const float* __restrict__ bc,
                                                 float* __restrict__ out, int N) {
    __shared__ int isLast;
    int t = blockIdx.x * blockDim.x + threadIdx.x;
    int tid = threadIdx.x;
    int node = t >> 5;
    if (node < N) {
        int lane = t & 31;
        const unsigned* hp = (const unsigned*)g_hH;
        float2 self = h2f(hp[(size_t)node * 32 + lane]);
        float a0 = self.x, a1 = self.y;
        int beg = g_offs[node], end = g_offs[node + 1];
        int j = beg;
        for (; j < end && (j & 3); j++) {
            int s = __ldg(&g_csrc[j]);
            float2 f = h2f(__ldg(&hp[(size_t)s * 32 + lane]));
            a0 += f.x; a1 += f.y;
        }
        for (; j + 7 < end; j += 8) {
            int4 iA = *(const int4*)&g_csrc[j];
            int4 iB = *(const int4*)&g_csrc[j + 4];
            float2 f0 = h2f(__ldg(&hp[(size_t)iA.x * 32 + lane]));
            float2 f1 = h2f(__ldg(&hp[(size_t)iA.y * 32 + lane]));
            float2 f2 = h2f(__ldg(&hp[(size_t)iA.z * 32 + lane]));
            float2 f3 = h2f(__ldg(&hp[(size_t)iA.w * 32 + lane]));
            float2 f4 = h2f(__ldg(&hp[(size_t)iB.x * 32 + lane]));
            float2 f5 = h2f(__ldg(&hp[(size_t)iB.y * 32 + lane]));
            float2 f6 = h2f(__ldg(&hp[(size_t)iB.z * 32 + lane]));
            float2 f7 = h2f(__ldg(&hp[(size_t)iB.w * 32 + lane]));
            a0 += ((f0.x + f1.x) + (f2.x + f3.x)) + ((f4.x + f5.x) + (f6.x + f7.x));
            a1 += ((f0.y + f1.y) + (f2.y + f3.y)) + ((f4.y + f5.y) + (f6.y + f7.y));
        }
        for (; j + 3 < end; j += 4) {
            int4 iA = *(const int4*)&g_csrc[j];
            float2 f0 = h2f(__ldg(&hp[(size_t)iA.x * 32 + lane]));
            float2 f1 = h2f(__ldg(&hp[(size_t)iA.y * 32 + lane]));
            float2 f2 = h2f(__ldg(&hp[(size_t)iA.z * 32 + lane]));
            float2 f3 = h2f(__ldg(&hp[(size_t)iA.w * 32 + lane]));
            a0 += (f0.x + f1.x) + (f2.x + f3.x);
            a1 += (f0.y + f1.y) + (f2.y + f3.y);
        }
        for (; j < end; j++) {
            int s = __ldg(&g_csrc[j]);
            float2 f = h2f(__ldg(&hp[(size_t)s * 32 + lane]));
            a0 += f.x; a1 += f.y;
        }
        float dd = g_dinv[node];
        int c = lane * 2;
        float y0 = fmaxf(0.f, a0 * dd * g_sc2[c + 0] + g_sh2[c + 0]);
        float y1 = fmaxf(0.f, a1 * dd * g_sc2[c + 1] + g_sh2[c + 1]);
        int g = batch[node];
        red_add_v2(&g_pooled[g * D + c], y0, y1);
        if (lane == 0) atomicAdd(&g_cnt[g], 1.0f);
    }

    // last-block-does-classifier
    __threadfence();
    __syncthreads();
    if (tid == 0) {
        unsigned old = atomicAdd(&g_done, 1u);
        isLast = (old == gridDim.x - 1u) ? 1 : 0;
    }
    __syncthreads();
    if (isLast) {
        __threadfence();                      // acquire all blocks' reds
        if (tid < NGRAPH * 2) {
            int g = tid >> 1, o = tid & 1;
            float inv = 1.f / fmaxf(g_cnt[g], 1.f);
            float s = 0.f;
#pragma unroll
            for (int d = 0; d < D; d++) s += g_pooled[g * D + d] * Wc[d * 2 + o];
            out[tid] = s * inv + bc[o];
        }
        __syncthreads();
        for (int i = tid; i < NGRAPH * D; i += 256) g_pooled[i] = 0.f;
        if (tid < NGRAPH) g_cnt[tid] = 0.f;
        if (tid == 0) g_done = 0;
    }
}

// ---------------- host orchestration (fork/join, 8 launches) ---------------
extern "C" void kernel_launch(void* const* d_in, const int* in_sizes, int n_in,
                              void* d_out, int out_size) {
    const float* x   = (const float*)d_in[0];
    const int*   ei  = (const int*)d_in[1];
    const int*   bat = (const int*)d_in[2];
    const float* W1  = (const float*)d_in[3];
    const float* b1  = (const float*)d_in[4];
    const float* g1  = (const float*)d_in[5];
    const float* be1 = (const float*)d_in[6];
    const float* m1  = (const float*)d_in[7];
    const float* v1  = (const float*)d_in[8];
    const float* W2  = (const float*)d_in[9];
    const float* b2  = (const float*)d_in[10];
    const float* g2  = (const float*)d_in[11];
    const float* be2 = (const float*)d_in[12];
    const float* m2  = (const float*)d_in[13];
    const float* v2  = (const float*)d_in[14];
    const float* Wc  = (const float*)d_in[15];
    const float* bc  = (const float*)d_in[16];
    float* out = (float*)d_out;

    int N = in_sizes[0] / D;
    int E = in_sizes[1] / 2;
    const int* src = ei;
    const int* dst = ei + E;

    __half *hH;
    cudaGetSymbolAddress((void**)&hH, g_hH);
    __half *hG;
    cudaGetSymbolAddress((void**)&hG, g_hG);

    int nb_edges  = (E + 255) / 256;
    int nb_node32 = (int)(((long long)N * 32 + 255) / 256);
    int nb_gemm1  = (N + 63) / 64;
    int nb_gemm2  = (N + 127) / 128;
    int nblk_scan = (N + 1023) / 1024;

    static cudaStream_t sB = nullptr;
    static cudaEvent_t eFork = nullptr, eScan = nullptr, eFill = nullptr;
    if (!sB) {
        cudaStreamCreateWithFlags(&sB, cudaStreamNonBlocking);
        cudaEventCreateWithFlags(&eFork, cudaEventDisableTiming);
        cudaEventCreateWithFlags(&eScan, cudaEventDisableTiming);
        cudaEventCreateWithFlags(&eFill, cudaEventDisableTiming);
    }

    // fork
    cudaEventRecord(eFork, 0);
    cudaStreamWaitEvent(sB, eFork, 0);

    // A: GEMM1 (unscaled fp16 out), concurrent with B's CSR chain
    k_gemm1<<<nb_gemm1, 256>>>(x, W1, hH, N);

    // B: cnt -> scan -> fill
    k_cnt<<<nb_edges, 256, 0, sB>>>(dst, E);
    k_scanLB<<<nblk_scan, 256, 0, sB>>>(b1, g1, be1, m1, v1,
                                        b2, g2, be2, m2, v2, N, E);
    cudaEventRecord(eScan, sB);
    k_fill<<<nb_edges, 256, 0, sB>>>(src, dst, E);
    cudaEventRecord(eFill, sB);

    // A: prescale rows by dinv (needs scan + gemm1), concurrent with fill
    cudaStreamWaitEvent(0, eScan, 0);
    k_scale<<<nb_node32, 256>>>(N);

    // A: join with fill, then layer-1 gather
    cudaStreamWaitEvent(0, eFill, 0);
    k_agg1<<<nb_node32, 256>>>(N);

    // A: tensor-core GEMM2 (hi+residual fp16 weights, dinv-scaled out)
    k_gemm2tc<<<nb_gemm2, 256>>>(hG, W2, hH, N);

    // A: layer-2 gather + pool + (last block) classifier
    k_agg2cls<<<nb_node32, 256>>>(bat, Wc, bc, out, N);
}

// round 11
// speedup vs baseline: 1.1084x; 1.0901x over previous
#include <cuda_runtime.h>
#include <cuda_fp16.h>

#define NMAX   100000
#define EMAX   1200000
#define NGRAPH 64
#define D      64
#define NBLK_SCAN 128   // >= ceil(NMAX/1024)

// ---------------- device scratch (no allocations allowed) ----------------
// INVARIANT at entry of every call: g_cntI==0, g_pooled==0, g_cnt==0, g_done==0.
// g_lbFlag is reset by k_cnt (block 0) before k_scanLB runs.
__device__ __align__(16) __half g_hH[(size_t)NMAX * D];   // pre-agg rows (fp16)
__device__ __align__(16) __half g_hG[(size_t)NMAX * D];   // h1 rows (fp16)
__device__ float g_dinv[NMAX];
__device__ __align__(16) float g_pooled[NGRAPH * D];
__device__ float g_cnt[NGRAPH];
__device__ float g_sc1[D], g_sh1[D], g_sc2[D], g_sh2[D];

__device__ int g_cntI[NMAX];
__device__ int g_offs[NMAX + 1];
__device__ int g_cursor[NMAX];
__device__ __align__(16) int g_csrc[EMAX];
__device__ volatile unsigned g_lbFlag[NBLK_SCAN];  // status(2b)<<30 | sum
__device__ unsigned g_done;

__device__ __forceinline__ void red_add_v4(float* addr, float a, float b,
                                           float c, float d) {
    asm volatile("red.global.add.v4.f32 [%0], {%1,%2,%3,%4};"
                 :: "l"(addr), "f"(a), "f"(b), "f"(c), "f"(d) : "memory");
}

__device__ __forceinline__ float2 h2f(unsigned raw) {
    return __half22float2(*(__half2*)&raw);
}

__device__ __forceinline__ unsigned f2h(float a, float b) {
    __half2 p = __floats2half2_rn(a, b);
    return *(unsigned*)&p;
}

__device__ __forceinline__ float4 h4_to_f4(uint2 raw) {
    float2 f0 = __half22float2(*(__half2*)&raw.x);
    float2 f1 = __half22float2(*(__half2*)&raw.y);
    return make_float4(f0.x, f0.y, f1.x, f1.y);
}

__device__ __forceinline__ uint2 f4_to_h4(float a, float b, float c, float d) {
    uint2 u;
    u.x = f2h(a, b);
    u.y = f2h(c, d);
    return u;
}

__device__ __forceinline__ void mma16816(float* c, unsigned a0, unsigned a1,
                                         unsigned a2, unsigned a3,
                                         unsigned b0, unsigned b1) {
    asm volatile(
        "mma.sync.aligned.m16n8k16.row.col.f32.f16.f16.f32 "
        "{%0,%1,%2,%3}, {%4,%5,%6,%7}, {%8,%9}, {%0,%1,%2,%3};"
        : "+f"(c[0]), "+f"(c[1]), "+f"(c[2]), "+f"(c[3])
        : "r"(a0), "r"(a1), "r"(a2), "r"(a3), "r"(b0), "r"(b1));
}

// ---------------- in-degree histogram + lookback-flag reset ----------------
__global__ void k_cnt(const int* __restrict__ dst, int E) {
    if (blockIdx.x == 0 && threadIdx.x < NBLK_SCAN)
        g_lbFlag[threadIdx.x] = 0;
    int e = blockIdx.x * blockDim.x + threadIdx.x;
    if (e < E) atomicAdd(&g_cntI[dst[e]], 1);
}

// ------- decoupled look-back scan + dinv + BN fold + resets ----------------
__global__ void __launch_bounds__(256) k_scanLB(
        const float* __restrict__ b1, const float* __restrict__ g1,
        const float* __restrict__ be1, const float* __restrict__ m1,
        const float* __restrict__ v1,
        const float* __restrict__ b2, const float* __restrict__ g2,
        const float* __restrict__ be2, const float* __restrict__ m2,
        const float* __restrict__ v2, int N, int E) {
    __shared__ int wsum[8];
    __shared__ unsigned exS;
    __shared__ int totS;
    int tid = threadIdx.x, bid = blockIdx.x;
    int lane = tid & 31, w = tid >> 5;
    int base = bid * 1024 + tid * 4;

    int v0 = 0, vv1 = 0, vv2 = 0, vv3 = 0;
    if (base + 0 < N) v0  = g_cntI[base + 0];
    if (base + 1 < N) vv1 = g_cntI[base + 1];
    if (base + 2 < N) vv2 = g_cntI[base + 2];
    if (base + 3 < N) vv3 = g_cntI[base + 3];
    int s = v0 + vv1 + vv2 + vv3;

    int inc = s;
#pragma unroll
    for (int o = 1; o < 32; o <<= 1) {
        int y = __shfl_up_sync(0xffffffff, inc, o);
        if (lane >= o) inc += y;
    }
    if (lane == 31) wsum[w] = inc;
    __syncthreads();
    if (tid == 0) {
        int run = 0;
#pragma unroll
        for (int i = 0; i < 8; i++) { int xv = wsum[i]; wsum[i] = run; run += xv; }
        totS = run;
        unsigned pack = (bid == 0 ? (2u << 30) : (1u << 30)) | (unsigned)run;
        atomicExch((unsigned*)&g_lbFlag[bid], pack);
    }
    __syncthreads();
    int blkEx = wsum[w] + inc - s;
    int total = totS;

    if (bid > 0) {
        if (w == 0) {
            unsigned ex = 0;
            int wnd = bid;
            for (;;) {
                int idx = wnd - 32 + lane;
                unsigned f = (1u << 30);
                if (idx >= 0) {
                    do { f = g_lbFlag[idx]; } while ((f >> 30) == 0);
                }
                unsigned isPref = __ballot_sync(0xffffffff, idx >= 0 && (f >> 30) == 2u);
                int cut = isPref ? (31 - __clz(isPref)) : -1;
                unsigned val = (lane >= cut) ? (f & 0x3FFFFFFFu) : 0u;
#pragma unroll
                for (int o = 16; o; o >>= 1) val += __shfl_down_sync(0xffffffff, val, o);
                if (lane == 0) ex += val;
                if (cut >= 0) break;
                wnd -= 32;
            }
            if (lane == 0) {
                exS = ex;
                atomicExch((unsigned*)&g_lbFlag[bid], (2u << 30) | (ex + (unsigned)total));
            }
        }
        __syncthreads();
    } else if (tid == 0) {
        exS = 0;
    }
    __syncthreads();
    unsigned ex = exS;

    int o = (int)ex + blkEx;
    if (base + 0 < N) { g_offs[base+0]=o; g_cursor[base+0]=o; g_dinv[base+0]=rsqrtf((float)v0 +1.f); g_cntI[base+0]=0; o+=v0;  }
    if (base + 1 < N) { g_offs[base+1]=o; g_cursor[base+1]=o; g_dinv[base+1]=rsqrtf((float)vv1+1.f); g_cntI[base+1]=0; o+=vv1; }
    if (base + 2 < N) { g_offs[base+2]=o; g_cursor[base+2]=o; g_dinv[base+2]=rsqrtf((float)vv2+1.f); g_cntI[base+2]=0; o+=vv2; }
    if (base + 3 < N) { g_offs[base+3]=o; g_cursor[base+3]=o; g_dinv[base+3]=rsqrtf((float)vv3+1.f); g_cntI[base+3]=0; }

    if (bid == 0 && tid == 0) g_offs[N] = E;
    if (bid == 0 && tid < D) {
        float s1 = g1[tid] * rsqrtf(v1[tid] + 1e-5f);
        g_sc1[tid] = s1;
        g_sh1[tid] = (b1[tid] - m1[tid]) * s1 + be1[tid];
        float s2 = g2[tid] * rsqrtf(v2[tid] + 1e-5f);
        g_sc2[tid] = s2;
        g_sh2[tid] = (b2[tid] - m2[tid]) * s2 + be2[tid];
    }
}

// ---------------- fill CSR ----------------
__global__ void k_fill(const int* __restrict__ src, const int* __restrict__ dst, int E) {
    int e = blockIdx.x * blockDim.x + threadIdx.x;
    if (e < E) {
        int d = dst[e];
        int p = atomicAdd(&g_cursor[d], 1);
        g_csrc[p] = src[e];
    }
}

// ---------------- GEMM1 core macro ----------------
#define GEMM_ROW(ai, i)                                                           \
    acc[i][0] = fmaf(ai.w, w3.x, fmaf(ai.z, w2.x, fmaf(ai.y, w1.x, fmaf(ai.x, w0.x, acc[i][0])))); \
    acc[i][1] = fmaf(ai.w, w3.y, fmaf(ai.z, w2.y, fmaf(ai.y, w1.y, fmaf(ai.x, w0.y, acc[i][1])))); \
    acc[i][2] = fmaf(ai.w, w3.z, fmaf(ai.z, w2.z, fmaf(ai.y, w1.z, fmaf(ai.x, w0.z, acc[i][2])))); \
    acc[i][3] = fmaf(ai.w, w3.w, fmaf(ai.z, w2.w, fmaf(ai.y, w1.w, fmaf(ai.x, w0.w, acc[i][3]))));

// ------- GEMM1: C_h[N,64] = fp16(A_f32 @ W1) (runs ∥ CSR chain) ------------
__global__ void __launch_bounds__(256) k_gemm1(const float* __restrict__ A,
                                               const float* __restrict__ W,
                                               __half* __restrict__ C, int N) {
    __shared__ __align__(16) float Ws[D * D];
    __shared__ __align__(16) float As[64 * 68];
    int tid = threadIdx.x;
    int row0 = blockIdx.x * 64;

    float4* Ws4 = (float4*)Ws;
    const float4* W4 = (const float4*)W;
#pragma unroll
    for (int i = 0; i < 4; i++) Ws4[tid + i * 256] = W4[tid + i * 256];

#pragma unroll
    for (int i = 0; i < 4; i++) {
        int idx = tid + i * 256;
        int r = idx >> 4, c4 = idx & 15;
        float4 a = make_float4(0.f, 0.f, 0.f, 0.f);
        if (row0 + r < N)
            a = __ldcs((const float4*)(A + (size_t)(row0 + r) * D) + c4);
        ((float4*)&As[r * 68])[c4] = a;
    }
    __syncthreads();

    int tx = tid & 15, ty = tid >> 4;
    float acc[4][4];
#pragma unroll
    for (int i = 0; i < 4; i++)
#pragma unroll
        for (int j = 0; j < 4; j++) acc[i][j] = 0.f;

    const float4* A0 = (const float4*)&As[(ty * 4 + 0) * 68];
    const float4* A1 = (const float4*)&As[(ty * 4 + 1) * 68];
    const float4* A2 = (const float4*)&As[(ty * 4 + 2) * 68];
    const float4* A3 = (const float4*)&As[(ty * 4 + 3) * 68];

#pragma unroll
    for (int k4 = 0; k4 < 16; k4++) {
        float4 w0 = Ws4[(4 * k4 + 0) * 16 + tx];
        float4 w1 = Ws4[(4 * k4 + 1) * 16 + tx];
        float4 w2 = Ws4[(4 * k4 + 2) * 16 + tx];
        float4 w3 = Ws4[(4 * k4 + 3) * 16 + tx];
        float4 a0 = A0[k4], a1 = A1[k4], a2 = A2[k4], a3 = A3[k4];
        GEMM_ROW(a0, 0)
        GEMM_ROW(a1, 1)
        GEMM_ROW(a2, 2)
        GEMM_ROW(a3, 3)
    }

#pragma unroll
    for (int i = 0; i < 4; i++) {
        int r = row0 + ty * 4 + i;
        if (r < N)
            ((uint2*)(C + (size_t)r * D))[tx] =
                f4_to_h4(acc[i][0], acc[i][1], acc[i][2], acc[i][3]);
    }
}

// -------- layer-1 gather: 16 threads/node, fp16 rows, per-edge dinv --------
__global__ void __launch_bounds__(256) k_agg1(int N) {
    int t = blockIdx.x * blockDim.x + threadIdx.x;
    int node = t >> 4;
    if (node >= N) return;
    int c4 = t & 15;
    const uint2* hp = (const uint2*)g_hH;   // row = 16 uint2
    float dd = g_dinv[node];
    float4 sf = h4_to_f4(hp[(size_t)node * 16 + c4]);
    float a0 = dd * sf.x, a1 = dd * sf.y, a2 = dd * sf.z, a3 = dd * sf.w;
    int beg = g_offs[node], end = g_offs[node + 1];
    int j = beg;
    for (; j + 3 < end; j += 4) {
        int i0 = __ldg(&g_csrc[j + 0]);
        int i1 = __ldg(&g_csrc[j + 1]);
        int i2 = __ldg(&g_csrc[j + 2]);
        int i3 = __ldg(&g_csrc[j + 3]);
        float w0 = __ldg(&g_dinv[i0]);
        float w1 = __ldg(&g_dinv[i1]);
        float w2 = __ldg(&g_dinv[i2]);
        float w3 = __ldg(&g_dinv[i3]);
        float4 f0 = h4_to_f4(__ldg(&hp[(size_t)i0 * 16 + c4]));
        float4 f1 = h4_to_f4(__ldg(&hp[(size_t)i1 * 16 + c4]));
        float4 f2 = h4_to_f4(__ldg(&hp[(size_t)i2 * 16 + c4]));
        float4 f3 = h4_to_f4(__ldg(&hp[(size_t)i3 * 16 + c4]));
        a0 += w0 * f0.x + w1 * f1.x + w2 * f2.x + w3 * f3.x;
        a1 += w0 * f0.y + w1 * f1.y + w2 * f2.y + w3 * f3.y;
        a2 += w0 * f0.z + w1 * f1.z + w2 * f2.z + w3 * f3.z;
        a3 += w0 * f0.w + w1 * f1.w + w2 * f2.w + w3 * f3.w;
    }
    for (; j < end; j++) {
        int i0 = __ldg(&g_csrc[j]);
        float w0 = __ldg(&g_dinv[i0]);
        float4 f0 = h4_to_f4(__ldg(&hp[(size_t)i0 * 16 + c4]));
        a0 += w0 * f0.x; a1 += w0 * f0.y; a2 += w0 * f0.z; a3 += w0 * f0.w;
    }
    int c = c4 * 4;
    float y0 = fmaxf(0.f, a0 * dd * g_sc1[c + 0] + g_sh1[c + 0]);
    float y1 = fmaxf(0.f, a1 * dd * g_sc1[c + 1] + g_sh1[c + 1]);
    float y2 = fmaxf(0.f, a2 * dd * g_sc1[c + 2] + g_sh1[c + 2]);
    float y3 = fmaxf(0.f, a3 * dd * g_sc1[c + 3] + g_sh1[c + 3]);
    ((uint2*)g_hG)[(size_t)node * 16 + c4] = f4_to_h4(y0, y1, y2, y3);
}

// ------- GEMM2 tensor-core: hH = fp16((hG @ W2) * dinv), W2 split hi+res ---
__global__ void __launch_bounds__(256) k_gemm2tc(const __half* __restrict__ A,
                                                 const float* __restrict__ W,
                                                 __half* __restrict__ C, int N) {
    __shared__ __align__(16) __half As[128 * 72];
    __shared__ __align__(16) __half Wh[64 * 72];
    __shared__ __align__(16) __half Wr[64 * 72];
    int tid = threadIdx.x;
    int warp = tid >> 5, lane = tid & 31;
    int row0 = blockIdx.x * 128;

    // W2 -> fp16 hi + fp16 residual, transposed [n][k]
#pragma unroll
    for (int i = 0; i < 16; i++) {
        int idx = tid + i * 256;
        int k = idx >> 6, n = idx & 63;
        float w = W[k * 64 + n];
        __half wh = __float2half_rn(w);
        Wh[n * 72 + k] = wh;
        Wr[n * 72 + k] = __float2half_rn(w - __half2float(wh));
    }

    // A tile: 128 rows x 64 halves, row stride 72 halves
#pragma unroll
    for (int i = 0; i < 4; i++) {
        int idx = tid + i * 256;
        int r = idx >> 3, c8 = idx & 7;
        uint4 raw = make_uint4(0u, 0u, 0u, 0u);
        if (row0 + r < N)
            raw = __ldcs((const uint4*)(A + (size_t)(row0 + r) * D) + c8);
        *(uint4*)&As[r * 72 + c8 * 8] = raw;
    }
    __syncthreads();

    int g = lane >> 2, tg = lane & 3;
    int rbase = warp * 16;
    float acc[8][4];
#pragma unroll
    for (int nt = 0; nt < 8; nt++)
#pragma unroll
        for (int i = 0; i < 4; i++) acc[nt][i] = 0.f;

#pragma unroll
    for (int k0 = 0; k0 < 64; k0 += 16) {
        unsigned ra0 = *(const unsigned*)&As[(rbase + g) * 72 + k0 + tg * 2];
        unsigned ra1 = *(const unsigned*)&As[(rbase + g + 8) * 72 + k0 + tg * 2];
        unsigned ra2 = *(const unsigned*)&As[(rbase + g) * 72 + k0 + tg * 2 + 8];
        unsigned ra3 = *(const unsigned*)&As[(rbase + g + 8) * 72 + k0 + tg * 2 + 8];
#pragma unroll
        for (int nt = 0; nt < 8; nt++) {
            int nrow = (nt * 8 + g) * 72 + k0 + tg * 2;
            unsigned bh0 = *(const unsigned*)&Wh[nrow];
            unsigned bh1 = *(const unsigned*)&Wh[nrow + 8];
            mma16816(acc[nt], ra0, ra1, ra2, ra3, bh0, bh1);
            unsigned br0 = *(const unsigned*)&Wr[nrow];
            unsigned br1 = *(const unsigned*)&Wr[nrow + 8];
            mma16816(acc[nt], ra0, ra1, ra2, ra3, br0, br1);
        }
    }

    int r0g = row0 + rbase + g;
    int r1g = r0g + 8;
    float d0 = (r0g < N) ? g_dinv[r0g] : 0.f;
    float d1 = (r1g < N) ? g_dinv[r1g] : 0.f;
#pragma unroll
    for (int nt = 0; nt < 8; nt++) {
        int n = nt * 8 + tg * 2;
        if (r0g < N)
            *(unsigned*)(C + (size_t)r0g * D + n) = f2h(acc[nt][0] * d0, acc[nt][1] * d0);
        if (r1g < N)
            *(unsigned*)(C + (size_t)r1g * D + n) = f2h(acc[nt][2] * d1, acc[nt][3] * d1);
    }
}

// ------- agg2 (16T/node) + BN2 + ReLU + pool + last-block classifier -------
__global__ void __launch_bounds__(256) k_agg2cls(const int* __restrict__ batch,
                                                 const float* __restrict__ Wc,
                                                 const float* __restrict__ bc,
                                                 float* __restrict__ out, int N) {
    __shared__ int isLast;
    int t = blockIdx.x * blockDim.x + threadIdx.x;
    int tid = threadIdx.x;
    int node = t >> 4;
    if (node < N) {
        int c4 = t & 15;
        const uint2* hp = (const uint2*)g_hH;
        float4 sf = h4_to_f4(hp[(size_t)node * 16 + c4]);
        float a0 = sf.x, a1 = sf.y, a2 = sf.z, a3 = sf.w;
        int beg = g_offs[node], end = g_offs[node + 1];
        int j = beg;
        for (; j + 3 < end; j += 4) {
            int i0 = __ldg(&g_csrc[j + 0]);
            int i1 = __ldg(&g_csrc[j + 1]);
            int i2 = __ldg(&g_csrc[j + 2]);
            int i3 = __ldg(&g_csrc[j + 3]);
            float4 f0 = h4_to_f4(__ldg(&hp[(size_t)i0 * 16 + c4]));
            float4 f1 = h4_to_f4(__ldg(&hp[(size_t)i1 * 16 + c4]));
            float4 f2 = h4_to_f4(__ldg(&hp[(size_t)i2 * 16 + c4]));
            float4 f3 = h4_to_f4(__ldg(&hp[(size_t)i3 * 16 + c4]));
            a0 += (f0.x + f1.x) + (f2.x + f3.x);
            a1 += (f0.y + f1.y) + (f2.y + f3.y);
            a2 += (f0.z + f1.z) + (f2.z + f3.z);
            a3 += (f0.w + f1.w) + (f2.w + f3.w);
        }
        for (; j < end; j++) {
            int i0 = __ldg(&g_csrc[j]);
            float4 f0 = h4_to_f4(__ldg(&hp[(size_t)i0 * 16 + c4]));
            a0 += f0.x; a1 += f0.y; a2 += f0.z; a3 += f0.w;
        }
        float dd = g_dinv[node];
        int c = c4 * 4;
        float y0 = fmaxf(0.f, a0 * dd * g_sc2[c + 0] + g_sh2[c + 0]);
        float y1 = fmaxf(0.f, a1 * dd * g_sc2[c + 1] + g_sh2[c + 1]);
        float y2 = fmaxf(0.f, a2 * dd * g_sc2[c + 2] + g_sh2[c + 2]);
        float y3 = fmaxf(0.f, a3 * dd * g_sc2[c + 3] + g_sh2[c + 3]);
        int g = batch[node];
        red_add_v4(&g_pooled[g * D + c], y0, y1, y2, y3);
        if (c4 == 0) atomicAdd(&g_cnt[g], 1.0f);
    }

    // last-block-does-classifier
    __threadfence();
    __syncthreads();
    if (tid == 0) {
        unsigned old = atomicAdd(&g_done, 1u);
        isLast = (old == gridDim.x - 1u) ? 1 : 0;
    }
    __syncthreads();
    if (isLast) {
        __threadfence();                      // acquire all blocks' reds
        if (tid < NGRAPH * 2) {
            int g = tid >> 1, o = tid & 1;
            float inv = 1.f / fmaxf(g_cnt[g], 1.f);
            float s = 0.f;
#pragma unroll
            for (int d = 0; d < D; d++) s += g_pooled[g * D + d] * Wc[d * 2 + o];
            out[tid] = s * inv + bc[o];
        }
        __syncthreads();
        for (int i = tid; i < NGRAPH * D; i += 256) g_pooled[i] = 0.f;
        if (tid < NGRAPH) g_cnt[tid] = 0.f;
        if (tid == 0) g_done = 0;
    }
}

// ---------------- host orchestration (R6 fork/join, 7 launches) ------------
extern "C" void kernel_launch(void* const* d_in, const int* in_sizes, int n_in,
                              void* d_out, int out_size) {
    const float* x   = (const float*)d_in[0];
    const int*   ei  = (const int*)d_in[1];
    const int*   bat = (const int*)d_in[2];
    const float* W1  = (const float*)d_in[3];
    const float* b1  = (const float*)d_in[4];
    const float* g1  = (const float*)d_in[5];
    const float* be1 = (const float*)d_in[6];
    const float* m1  = (const float*)d_in[7];
    const float* v1  = (const float*)d_in[8];
    const float* W2  = (const float*)d_in[9];
    const float* b2  = (const float*)d_in[10];
    const float* g2  = (const float*)d_in[11];
    const float* be2 = (const float*)d_in[12];
    const float* m2  = (const float*)d_in[13];
    const float* v2  = (const float*)d_in[14];
    const float* Wc  = (const float*)d_in[15];
    const float* bc  = (const float*)d_in[16];
    float* out = (float*)d_out;

    int N = in_sizes[0] / D;
    int E = in_sizes[1] / 2;
    const int* src = ei;
    const int* dst = ei + E;

    __half *hH, *hG;
    cudaGetSymbolAddress((void**)&hH, g_hH);
    cudaGetSymbolAddress((void**)&hG, g_hG);

    int nb_edges  = (E + 255) / 256;
    int nb_node16 = (int)(((long long)N * 16 + 255) / 256);
    int nb_gemm1  = (N + 63) / 64;
    int nb_gemm2  = (N + 127) / 128;
    int nblk_scan = (N + 1023) / 1024;

    static cudaStream_t s2 = nullptr;
    static cudaEvent_t eFork = nullptr, eJoin = nullptr;
    if (!s2) {
        cudaStreamCreateWithFlags(&s2, cudaStreamNonBlocking);
        cudaEventCreateWithFlags(&eFork, cudaEventDisableTiming);
        cudaEventCreateWithFlags(&eJoin, cudaEventDisableTiming);
    }

    // fork: GEMM1 on s2 runs concurrently with CSR chain on default stream
    cudaEventRecord(eFork, 0);
    cudaStreamWaitEvent(s2, eFork, 0);
    k_gemm1<<<nb_gemm1, 256, 0, s2>>>(x, W1, hH, N);      // #1
    cudaEventRecord(eJoin, s2);

    k_cnt<<<nb_edges, 256>>>(dst, E);                     // #2
    k_scanLB<<<nblk_scan, 256>>>(b1, g1, be1, m1, v1,
                                 b2, g2, be2, m2, v2, N, E); // #3
    k_fill<<<nb_edges, 256>>>(src, dst, E);               // #4

    cudaStreamWaitEvent(0, eJoin, 0);                     // join

    // layer 1 gather + BN1 + ReLU (16 threads/node, fp16)
    k_agg1<<<nb_node16, 256>>>(N);                        // #5

    // layer 2: tensor-core GEMM(W2), dinv-scaled fp16 out
    k_gemm2tc<<<nb_gemm2, 256>>>(hG, W2, hH, N);          // #6

    // layer-2 gather + BN2 + ReLU + pool + fused classifier
    k_agg2cls<<<nb_node16, 256>>>(bat, Wc, bc, out, N);   // #7
}

// round 13
// speedup vs baseline: 1.2223x; 1.1027x over previous
#include <cuda_runtime.h>
#include <cuda_fp16.h>

#define NMAX   100000
#define EMAX   1200000
#define NGRAPH 64
#define D      64
#define NBLK_SCAN 128   // >= ceil(NMAX/1024)

// ---------------- device scratch (no allocations allowed) ----------------
// INVARIANT at entry of every call: g_cntI==0, g_pooled==0, g_cnt==0, g_done==0.
// g_lbFlag is reset by k_cnt (block 0) before k_scanLB runs.
__device__ __align__(16) __half g_hH[(size_t)NMAX * D];   // pre-agg rows (fp16)
__device__ __align__(16) __half g_hG[(size_t)NMAX * D];   // h1 rows (fp16)
__device__ float g_dinv[NMAX];
__device__ __align__(16) float g_pooled[NGRAPH * D];
__device__ float g_cnt[NGRAPH];
__device__ float g_sc1[D], g_sh1[D], g_sc2[D], g_sh2[D];

__device__ int g_cntI[NMAX];
__device__ int g_offs[NMAX + 1];
__device__ int g_cursor[NMAX];
__device__ __align__(16) int g_csrc[EMAX];
__device__ volatile unsigned g_lbFlag[NBLK_SCAN];  // status(2b)<<30 | sum
__device__ unsigned g_done;

__device__ __forceinline__ void red_add_v4(float* addr, float a, float b,
                                           float c, float d) {
    asm volatile("red.global.add.v4.f32 [%0], {%1,%2,%3,%4};"
                 :: "l"(addr), "f"(a), "f"(b), "f"(c), "f"(d) : "memory");
}

__device__ __forceinline__ float2 h2f(unsigned raw) {
    return __half22float2(*(__half2*)&raw);
}

__device__ __forceinline__ unsigned f2h(float a, float b) {
    __half2 p = __floats2half2_rn(a, b);
    return *(unsigned*)&p;
}

__device__ __forceinline__ uint2 f4_to_h4(float a, float b, float c, float d) {
    uint2 u;
    u.x = f2h(a, b);
    u.y = f2h(c, d);
    return u;
}

// accumulate 8 halves (uint4) into acc[8], weighted / unweighted
__device__ __forceinline__ void acc8_w(float* acc, uint4 r, float wt) {
    float2 p0 = h2f(r.x), p1 = h2f(r.y), p2 = h2f(r.z), p3 = h2f(r.w);
    acc[0] = fmaf(wt, p0.x, acc[0]); acc[1] = fmaf(wt, p0.y, acc[1]);
    acc[2] = fmaf(wt, p1.x, acc[2]); acc[3] = fmaf(wt, p1.y, acc[3]);
    acc[4] = fmaf(wt, p2.x, acc[4]); acc[5] = fmaf(wt, p2.y, acc[5]);
    acc[6] = fmaf(wt, p3.x, acc[6]); acc[7] = fmaf(wt, p3.y, acc[7]);
}

__device__ __forceinline__ void acc8(float* acc, uint4 r) {
    float2 p0 = h2f(r.x), p1 = h2f(r.y), p2 = h2f(r.z), p3 = h2f(r.w);
    acc[0] += p0.x; acc[1] += p0.y; acc[2] += p1.x; acc[3] += p1.y;
    acc[4] += p2.x; acc[5] += p2.y; acc[6] += p3.x; acc[7] += p3.y;
}

__device__ __forceinline__ void mma16816(float* c, unsigned a0, unsigned a1,
                                         unsigned a2, unsigned a3,
                                         unsigned b0, unsigned b1) {
    asm volatile(
        "mma.sync.aligned.m16n8k16.row.col.f32.f16.f16.f32 "
        "{%0,%1,%2,%3}, {%4,%5,%6,%7}, {%8,%9}, {%0,%1,%2,%3};"
        : "+f"(c[0]), "+f"(c[1]), "+f"(c[2]), "+f"(c[3])
        : "r"(a0), "r"(a1), "r"(a2), "r"(a3), "r"(b0), "r"(b1));
}

// ---------------- in-degree histogram + lookback-flag reset ----------------
__global__ void k_cnt(const int* __restrict__ dst, int E) {
    if (blockIdx.x == 0 && threadIdx.x < NBLK_SCAN)
        g_lbFlag[threadIdx.x] = 0;
    int e = blockIdx.x * blockDim.x + threadIdx.x;
    if (e < E) atomicAdd(&g_cntI[dst[e]], 1);
}

// ------- decoupled look-back scan + dinv + BN fold + resets ----------------
__global__ void __launch_bounds__(256) k_scanLB(
        const float* __restrict__ b1, const float* __restrict__ g1,
        const float* __restrict__ be1, const float* __restrict__ m1,
        const float* __restrict__ v1,
        const float* __restrict__ b2, const float* __restrict__ g2,
        const float* __restrict__ be2, const float* __restrict__ m2,
        const float* __restrict__ v2, int N, int E) {
    __shared__ int wsum[8];
    __shared__ unsigned exS;
    __shared__ int totS;
    int tid = threadIdx.x, bid = blockIdx.x;
    int lane = tid & 31, w = tid >> 5;
    int base = bid * 1024 + tid * 4;

    int v0 = 0, vv1 = 0, vv2 = 0, vv3 = 0;
    if (base + 0 < N) v0  = g_cntI[base + 0];
    if (base + 1 < N) vv1 = g_cntI[base + 1];
    if (base + 2 < N) vv2 = g_cntI[base + 2];
    if (base + 3 < N) vv3 = g_cntI[base + 3];
    int s = v0 + vv1 + vv2 + vv3;

    int inc = s;
#pragma unroll
    for (int o = 1; o < 32; o <<= 1) {
        int y = __shfl_up_sync(0xffffffff, inc, o);
        if (lane >= o) inc += y;
    }
    if (lane == 31) wsum[w] = inc;
    __syncthreads();
    if (tid == 0) {
        int run = 0;
#pragma unroll
        for (int i = 0; i < 8; i++) { int xv = wsum[i]; wsum[i] = run; run += xv; }
        totS = run;
        unsigned pack = (bid == 0 ? (2u << 30) : (1u << 30)) | (unsigned)run;
        atomicExch((unsigned*)&g_lbFlag[bid], pack);
    }
    __syncthreads();
    int blkEx = wsum[w] + inc - s;
    int total = totS;

    if (bid > 0) {
        if (w == 0) {
            unsigned ex = 0;
            int wnd = bid;
            for (;;) {
                int idx = wnd - 32 + lane;
                unsigned f = (1u << 30);
                if (idx >= 0) {
                    do { f = g_lbFlag[idx]; } while ((f >> 30) == 0);
                }
                unsigned isPref = __ballot_sync(0xffffffff, idx >= 0 && (f >> 30) == 2u);
                int cut = isPref ? (31 - __clz(isPref)) : -1;
                unsigned val = (lane >= cut) ? (f & 0x3FFFFFFFu) : 0u;
#pragma unroll
                for (int o = 16; o; o >>= 1) val += __shfl_down_sync(0xffffffff, val, o);
                if (lane == 0) ex += val;
                if (cut >= 0) break;
                wnd -= 32;
            }
            if (lane == 0) {
                exS = ex;
                atomicExch((unsigned*)&g_lbFlag[bid], (2u << 30) | (ex + (unsigned)total));
            }
        }
        __syncthreads();
    } else if (tid == 0) {
        exS = 0;
    }
    __syncthreads();
    unsigned ex = exS;

    int o = (int)ex + blkEx;
    if (base + 0 < N) { g_offs[base+0]=o; g_cursor[base+0]=o; g_dinv[base+0]=rsqrtf((float)v0 +1.f); g_cntI[base+0]=0; o+=v0;  }
    if (base + 1 < N) { g_offs[base+1]=o; g_cursor[base+1]=o; g_dinv[base+1]=rsqrtf((float)vv1+1.f); g_cntI[base+1]=0; o+=vv1; }
    if (base + 2 < N) { g_offs[base+2]=o; g_cursor[base+2]=o; g_dinv[base+2]=rsqrtf((float)vv2+1.f); g_cntI[base+2]=0; o+=vv2; }
    if (base + 3 < N) { g_offs[base+3]=o; g_cursor[base+3]=o; g_dinv[base+3]=rsqrtf((float)vv3+1.f); g_cntI[base+3]=0; }

    if (bid == 0 && tid == 0) g_offs[N] = E;
    if (bid == 0 && tid < D) {
        float s1 = g1[tid] * rsqrtf(v1[tid] + 1e-5f);
        g_sc1[tid] = s1;
        g_sh1[tid] = (b1[tid] - m1[tid]) * s1 + be1[tid];
        float s2 = g2[tid] * rsqrtf(v2[tid] + 1e-5f);
        g_sc2[tid] = s2;
        g_sh2[tid] = (b2[tid] - m2[tid]) * s2 + be2[tid];
    }
}

// ---------------- fill CSR ----------------
__global__ void k_fill(const int* __restrict__ src, const int* __restrict__ dst, int E) {
    int e = blockIdx.x * blockDim.x + threadIdx.x;
    if (e < E) {
        int d = dst[e];
        int p = atomicAdd(&g_cursor[d], 1);
        g_csrc[p] = src[e];
    }
}

// ---------------- GEMM1 core macro ----------------
#define GEMM_ROW(ai, i)                                                           \
    acc[i][0] = fmaf(ai.w, w3.x, fmaf(ai.z, w2.x, fmaf(ai.y, w1.x, fmaf(ai.x, w0.x, acc[i][0])))); \
    acc[i][1] = fmaf(ai.w, w3.y, fmaf(ai.z, w2.y, fmaf(ai.y, w1.y, fmaf(ai.x, w0.y, acc[i][1])))); \
    acc[i][2] = fmaf(ai.w, w3.z, fmaf(ai.z, w2.z, fmaf(ai.y, w1.z, fmaf(ai.x, w0.z, acc[i][2])))); \
    acc[i][3] = fmaf(ai.w, w3.w, fmaf(ai.z, w2.w, fmaf(ai.y, w1.w, fmaf(ai.x, w0.w, acc[i][3]))));

// ------- GEMM1: C_h[N,64] = fp16(A_f32 @ W1) (runs ∥ CSR chain) ------------
__global__ void __launch_bounds__(256) k_gemm1(const float* __restrict__ A,
                                               const float* __restrict__ W,
                                               __half* __restrict__ C, int N) {
    __shared__ __align__(16) float Ws[D * D];
    __shared__ __align__(16) float As[64 * 68];
    int tid = threadIdx.x;
    int row0 = blockIdx.x * 64;

    float4* Ws4 = (float4*)Ws;
    const float4* W4 = (const float4*)W;
#pragma unroll
    for (int i = 0; i < 4; i++) Ws4[tid + i * 256] = W4[tid + i * 256];

#pragma unroll
    for (int i = 0; i < 4; i++) {
        int idx = tid + i * 256;
        int r = idx >> 4, c4 = idx & 15;
        float4 a = make_float4(0.f, 0.f, 0.f, 0.f);
        if (row0 + r < N)
            a = __ldcs((const float4*)(A + (size_t)(row0 + r) * D) + c4);
        ((float4*)&As[r * 68])[c4] = a;
    }
    __syncthreads();

    int tx = tid & 15, ty = tid >> 4;
    float acc[4][4];
#pragma unroll
    for (int i = 0; i < 4; i++)
#pragma unroll
        for (int j = 0; j < 4; j++) acc[i][j] = 0.f;

    const float4* A0 = (const float4*)&As[(ty * 4 + 0) * 68];
    const float4* A1 = (const float4*)&As[(ty * 4 + 1) * 68];
    const float4* A2 = (const float4*)&As[(ty * 4 + 2) * 68];
    const float4* A3 = (const float4*)&As[(ty * 4 + 3) * 68];

#pragma unroll
    for (int k4 = 0; k4 < 16; k4++) {
        float4 w0 = Ws4[(4 * k4 + 0) * 16 + tx];
        float4 w1 = Ws4[(4 * k4 + 1) * 16 + tx];
        float4 w2 = Ws4[(4 * k4 + 2) * 16 + tx];
        float4 w3 = Ws4[(4 * k4 + 3) * 16 + tx];
        float4 a0 = A0[k4], a1 = A1[k4], a2 = A2[k4], a3 = A3[k4];
        GEMM_ROW(a0, 0)
        GEMM_ROW(a1, 1)
        GEMM_ROW(a2, 2)
        GEMM_ROW(a3, 3)
    }

#pragma unroll
    for (int i = 0; i < 4; i++) {
        int r = row0 + ty * 4 + i;
        if (r < N)
            ((uint2*)(C + (size_t)r * D))[tx] =
                f4_to_h4(acc[i][0], acc[i][1], acc[i][2], acc[i][3]);
    }
}

// -------- layer-1 gather: 8 threads/node, uint4 (16B) lanes ----------------
__global__ void __launch_bounds__(256) k_agg1(int N) {
    int t = blockIdx.x * blockDim.x + threadIdx.x;
    int node = t >> 3;
    if (node >= N) return;
    int c8 = t & 7;
    const uint4* hp = (const uint4*)g_hH;   // row = 8 uint4
    float dd = g_dinv[node];
    float acc[8];
    {
        uint4 sr = hp[(size_t)node * 8 + c8];
        float2 p0 = h2f(sr.x), p1 = h2f(sr.y), p2 = h2f(sr.z), p3 = h2f(sr.w);
        acc[0] = dd * p0.x; acc[1] = dd * p0.y;
        acc[2] = dd * p1.x; acc[3] = dd * p1.y;
        acc[4] = dd * p2.x; acc[5] = dd * p2.y;
        acc[6] = dd * p3.x; acc[7] = dd * p3.y;
    }
    int beg = g_offs[node], end = g_offs[node + 1];
    int j = beg;
    for (; j + 3 < end; j += 4) {
        int i0 = __ldg(&g_csrc[j + 0]);
        int i1 = __ldg(&g_csrc[j + 1]);
        int i2 = __ldg(&g_csrc[j + 2]);
        int i3 = __ldg(&g_csrc[j + 3]);
        float w0 = __ldg(&g_dinv[i0]);
        float w1 = __ldg(&g_dinv[i1]);
        float w2 = __ldg(&g_dinv[i2]);
        float w3 = __ldg(&g_dinv[i3]);
        uint4 r0 = __ldg(&hp[(size_t)i0 * 8 + c8]);
        uint4 r1 = __ldg(&hp[(size_t)i1 * 8 + c8]);
        uint4 r2 = __ldg(&hp[(size_t)i2 * 8 + c8]);
        uint4 r3 = __ldg(&hp[(size_t)i3 * 8 + c8]);
        acc8_w(acc, r0, w0);
        acc8_w(acc, r1, w1);
        acc8_w(acc, r2, w2);
        acc8_w(acc, r3, w3);
    }
    for (; j < end; j++) {
        int i0 = __ldg(&g_csrc[j]);
        float w0 = __ldg(&g_dinv[i0]);
        uint4 r0 = __ldg(&hp[(size_t)i0 * 8 + c8]);
        acc8_w(acc, r0, w0);
    }
    int c = c8 * 8;
    uint4 outv;
    {
        float y0 = fmaxf(0.f, acc[0] * dd * g_sc1[c + 0] + g_sh1[c + 0]);
        float y1 = fmaxf(0.f, acc[1] * dd * g_sc1[c + 1] + g_sh1[c + 1]);
        float y2 = fmaxf(0.f, acc[2] * dd * g_sc1[c + 2] + g_sh1[c + 2]);
        float y3 = fmaxf(0.f, acc[3] * dd * g_sc1[c + 3] + g_sh1[c + 3]);
        float y4 = fmaxf(0.f, acc[4] * dd * g_sc1[c + 4] + g_sh1[c + 4]);
        float y5 = fmaxf(0.f, acc[5] * dd * g_sc1[c + 5] + g_sh1[c + 5]);
        float y6 = fmaxf(0.f, acc[6] * dd * g_sc1[c + 6] + g_sh1[c + 6]);
        float y7 = fmaxf(0.f, acc[7] * dd * g_sc1[c + 7] + g_sh1[c + 7]);
        outv.x = f2h(y0, y1); outv.y = f2h(y2, y3);
        outv.z = f2h(y4, y5); outv.w = f2h(y6, y7);
    }
    ((uint4*)g_hG)[(size_t)node * 8 + c8] = outv;
}

// ------- GEMM2 tensor-core: hH = fp16((hG @ W2) * dinv), W2 split hi+res ---
__global__ void __launch_bounds__(256) k_gemm2tc(const __half* __restrict__ A,
                                                 const float* __restrict__ W,
                                                 __half* __restrict__ C, int N) {
    __shared__ __align__(16) __half As[128 * 72];
    __shared__ __align__(16) __half Wh[64 * 72];
    __shared__ __align__(16) __half Wr[64 * 72];
    int tid = threadIdx.x;
    int warp = tid >> 5, lane = tid & 31;
    int row0 = blockIdx.x * 128;

    // W2 -> fp16 hi + fp16 residual, transposed [n][k]
#pragma unroll
    for (int i = 0; i < 16; i++) {
        int idx = tid + i * 256;
        int k = idx >> 6, n = idx & 63;
        float w = W[k * 64 + n];
        __half wh = __float2half_rn(w);
        Wh[n * 72 + k] = wh;
        Wr[n * 72 + k] = __float2half_rn(w - __half2float(wh));
    }

    // A tile: 128 rows x 64 halves, row stride 72 halves
#pragma unroll
    for (int i = 0; i < 4; i++) {
        int idx = tid + i * 256;
        int r = idx >> 3, c8 = idx & 7;
        uint4 raw = make_uint4(0u, 0u, 0u, 0u);
        if (row0 + r < N)
            raw = __ldcs((const uint4*)(A + (size_t)(row0 + r) * D) + c8);
        *(uint4*)&As[r * 72 + c8 * 8] = raw;
    }
    __syncthreads();

    int g = lane >> 2, tg = lane & 3;
    int rbase = warp * 16;
    float acc[8][4];
#pragma unroll
    for (int nt = 0; nt < 8; nt++)
#pragma unroll
        for (int i = 0; i < 4; i++) acc[nt][i] = 0.f;

#pragma unroll
    for (int k0 = 0; k0 < 64; k0 += 16) {
        unsigned ra0 = *(const unsigned*)&As[(rbase + g) * 72 + k0 + tg * 2];
        unsigned ra1 = *(const unsigned*)&As[(rbase + g + 8) * 72 + k0 + tg * 2];
        unsigned ra2 = *(const unsigned*)&As[(rbase + g) * 72 + k0 + tg * 2 + 8];
        unsigned ra3 = *(const unsigned*)&As[(rbase + g + 8) * 72 + k0 + tg * 2 + 8];
#pragma unroll
        for (int nt = 0; nt < 8; nt++) {
            int nrow = (nt * 8 + g) * 72 + k0 + tg * 2;
            unsigned bh0 = *(const unsigned*)&Wh[nrow];
            unsigned bh1 = *(const unsigned*)&Wh[nrow + 8];
            mma16816(acc[nt], ra0, ra1, ra2, ra3, bh0, bh1);
            unsigned br0 = *(const unsigned*)&Wr[nrow];
            unsigned br1 = *(const unsigned*)&Wr[nrow + 8];
            mma16816(acc[nt], ra0, ra1, ra2, ra3, br0, br1);
        }
    }

    int r0g = row0 + rbase + g;
    int r1g = r0g + 8;
    float d0 = (r0g < N) ? g_dinv[r0g] : 0.f;
    float d1 = (r1g < N) ? g_dinv[r1g] : 0.f;
#pragma unroll
    for (int nt = 0; nt < 8; nt++) {
        int n = nt * 8 + tg * 2;
        if (r0g < N)
            *(unsigned*)(C + (size_t)r0g * D + n) = f2h(acc[nt][0] * d0, acc[nt][1] * d0);
        if (r1g < N)
            *(unsigned*)(C + (size_t)r1g * D + n) = f2h(acc[nt][2] * d1, acc[nt][3] * d1);
    }
}

// ------- agg2 (8T/node uint4) + BN2 + ReLU + pool + last-block classifier --
__global__ void __launch_bounds__(256) k_agg2cls(const int* __restrict__ batch,
                                                 const float* __restrict__ Wc,
                                                 const float* __restrict__ bc,
                                                 float* __restrict__ out, int N) {
    __shared__ int isLast;
    int t = blockIdx.x * blockDim.x + threadIdx.x;
    int tid = threadIdx.x;
    int node = t >> 3;
    if (node < N) {
        int c8 = t & 7;
        const uint4* hp = (const uint4*)g_hH;
        float acc[8];
        {
            uint4 sr = hp[(size_t)node * 8 + c8];
            float2 p0 = h2f(sr.x), p1 = h2f(sr.y), p2 = h2f(sr.z), p3 = h2f(sr.w);
            acc[0] = p0.x; acc[1] = p0.y; acc[2] = p1.x; acc[3] = p1.y;
            acc[4] = p2.x; acc[5] = p2.y; acc[6] = p3.x; acc[7] = p3.y;
        }
        int beg = g_offs[node], end = g_offs[node + 1];
        int j = beg;
        for (; j + 3 < end; j += 4) {
            int i0 = __ldg(&g_csrc[j + 0]);
            int i1 = __ldg(&g_csrc[j + 1]);
            int i2 = __ldg(&g_csrc[j + 2]);
            int i3 = __ldg(&g_csrc[j + 3]);
            uint4 r0 = __ldg(&hp[(size_t)i0 * 8 + c8]);
            uint4 r1 = __ldg(&hp[(size_t)i1 * 8 + c8]);
            uint4 r2 = __ldg(&hp[(size_t)i2 * 8 + c8]);
            uint4 r3 = __ldg(&hp[(size_t)i3 * 8 + c8]);
            acc8(acc, r0);
            acc8(acc, r1);
            acc8(acc, r2);
            acc8(acc, r3);
        }
        for (; j < end; j++) {
            int i0 = __ldg(&g_csrc[j]);
            uint4 r0 = __ldg(&hp[(size_t)i0 * 8 + c8]);
            acc8(acc, r0);
        }
        float dd = g_dinv[node];
        int c = c8 * 8;
        float y0 = fmaxf(0.f, acc[0] * dd * g_sc2[c + 0] + g_sh2[c + 0]);
        float y1 = fmaxf(0.f, acc[1] * dd * g_sc2[c + 1] + g_sh2[c + 1]);
        float y2 = fmaxf(0.f, acc[2] * dd * g_sc2[c + 2] + g_sh2[c + 2]);
        float y3 = fmaxf(0.f, acc[3] * dd * g_sc2[c + 3] + g_sh2[c + 3]);
        float y4 = fmaxf(0.f, acc[4] * dd * g_sc2[c + 4] + g_sh2[c + 4]);
        float y5 = fmaxf(0.f, acc[5] * dd * g_sc2[c + 5] + g_sh2[c + 5]);
        float y6 = fmaxf(0.f, acc[6] * dd * g_sc2[c + 6] + g_sh2[c + 6]);
        float y7 = fmaxf(0.f, acc[7] * dd * g_sc2[c + 7] + g_sh2[c + 7]);
        int g = batch[node];
        red_add_v4(&g_pooled[g * D + c + 0], y0, y1, y2, y3);
        red_add_v4(&g_pooled[g * D + c + 4], y4, y5, y6, y7);
        if (c8 == 0) atomicAdd(&g_cnt[g], 1.0f);
    }

    // last-block-does-classifier
    __threadfence();
    __syncthreads();
    if (tid == 0) {
        unsigned old = atomicAdd(&g_done, 1u);
        isLast = (old == gridDim.x - 1u) ? 1 : 0;
    }
    __syncthreads();
    if (isLast) {
        __threadfence();                      // acquire all blocks' reds
        if (tid < NGRAPH * 2) {
            int g = tid >> 1, o = tid & 1;
            float inv = 1.f / fmaxf(g_cnt[g], 1.f);
            float s = 0.f;
#pragma unroll
            for (int d = 0; d < D; d++) s += g_pooled[g * D + d] * Wc[d * 2 + o];
            out[tid] = s * inv + bc[o];
        }
        __syncthreads();
        for (int i = tid; i < NGRAPH * D; i += 256) g_pooled[i] = 0.f;
        if (tid < NGRAPH) g_cnt[tid] = 0.f;
        if (tid == 0) g_done = 0;
    }
}

// ---------------- host orchestration (fork/join, 7 launches) ---------------
extern "C" void kernel_launch(void* const* d_in, const int* in_sizes, int n_in,
                              void* d_out, int out_size) {
    const float* x   = (const float*)d_in[0];
    const int*   ei  = (const int*)d_in[1];
    const int*   bat = (const int*)d_in[2];
    const float* W1  = (const float*)d_in[3];
    const float* b1  = (const float*)d_in[4];
    const float* g1  = (const float*)d_in[5];
    const float* be1 = (const float*)d_in[6];
    const float* m1  = (const float*)d_in[7];
    const float* v1  = (const float*)d_in[8];
    const float* W2  = (const float*)d_in[9];
    const float* b2  = (const float*)d_in[10];
    const float* g2  = (const float*)d_in[11];
    const float* be2 = (const float*)d_in[12];
    const float* m2  = (const float*)d_in[13];
    const float* v2  = (const float*)d_in[14];
    const float* Wc  = (const float*)d_in[15];
    const float* bc  = (const float*)d_in[16];
    float* out = (float*)d_out;

    int N = in_sizes[0] / D;
    int E = in_sizes[1] / 2;
    const int* src = ei;
    const int* dst = ei + E;

    __half *hH, *hG;
    cudaGetSymbolAddress((void**)&hH, g_hH);
    cudaGetSymbolAddress((void**)&hG, g_hG);

    int nb_edges  = (E + 255) / 256;
    int nb_node8  = (int)(((long long)N * 8 + 255) / 256);
    int nb_gemm1  = (N + 63) / 64;
    int nb_gemm2  = (N + 127) / 128;
    int nblk_scan = (N + 1023) / 1024;

    static cudaStream_t s2 = nullptr;
    static cudaEvent_t eFork = nullptr, eJoin = nullptr;
    if (!s2) {
        cudaStreamCreateWithFlags(&s2, cudaStreamNonBlocking);
        cudaEventCreateWithFlags(&eFork, cudaEventDisableTiming);
        cudaEventCreateWithFlags(&eJoin, cudaEventDisableTiming);
    }

    // fork: GEMM1 on s2 runs concurrently with CSR chain on default stream
    cudaEventRecord(eFork, 0);
    cudaStreamWaitEvent(s2, eFork, 0);
    k_gemm1<<<nb_gemm1, 256, 0, s2>>>(x, W1, hH, N);      // #1
    cudaEventRecord(eJoin, s2);

    k_cnt<<<nb_edges, 256>>>(dst, E);                     // #2
    k_scanLB<<<nblk_scan, 256>>>(b1, g1, be1, m1, v1,
                                 b2, g2, be2, m2, v2, N, E); // #3
    k_fill<<<nb_edges, 256>>>(src, dst, E);               // #4

    cudaStreamWaitEvent(0, eJoin, 0);                     // join

    // layer 1 gather + BN1 + ReLU (8 threads/node, uint4 lanes)
    k_agg1<<<nb_node8, 256>>>(N);                         // #5

    // layer 2: tensor-core GEMM(W2), dinv-scaled fp16 out
    k_gemm2tc<<<nb_gemm2, 256>>>(hG, W2, hH, N);          // #6

    // layer-2 gather + BN2 + ReLU + pool + fused classifier
    k_agg2cls<<<nb_node8, 256>>>(bat, Wc, bc, out, N);    // #7
}

// round 14
// speedup vs baseline: 1.2270x; 1.0039x over previous
#include <cuda_runtime.h>
#include <cuda_fp16.h>

#define NMAX   100000
#define EMAX   1200000
#define NGRAPH 64
#define D      64
#define NBLK_SCAN 128   // >= ceil(NMAX/1024)

// ---------------- device scratch (no allocations allowed) ----------------
// INVARIANT at entry of every call: g_cntI==0, g_pooled==0, g_cnt==0, g_done==0.
// g_lbFlag is reset by k_cnt (block 0) before k_scanLB runs.
__device__ __align__(16) __half g_hH[(size_t)NMAX * D];   // pre-agg rows (fp16)
__device__ __align__(16) __half g_hG[(size_t)NMAX * D];   // h1 rows (fp16)
__device__ float g_dinv[NMAX];
__device__ __align__(16) float g_pooled[NGRAPH * D];
__device__ float g_cnt[NGRAPH];
__device__ float g_sc1[D], g_sh1[D], g_sc2[D], g_sh2[D];

__device__ int g_cntI[NMAX];
__device__ int g_offs[NMAX + 1];
__device__ int g_cursor[NMAX];
__device__ __align__(16) int g_csrc[EMAX];
__device__ volatile unsigned g_lbFlag[NBLK_SCAN];  // status(2b)<<30 | sum
__device__ unsigned g_done;

__device__ __forceinline__ void red_add_v4(float* addr, float a, float b,
                                           float c, float d) {
    asm volatile("red.global.add.v4.f32 [%0], {%1,%2,%3,%4};"
                 :: "l"(addr), "f"(a), "f"(b), "f"(c), "f"(d) : "memory");
}

__device__ __forceinline__ void red_add_i(int* addr, int v) {
    asm volatile("red.global.add.s32 [%0], %1;" :: "l"(addr), "r"(v) : "memory");
}

__device__ __forceinline__ float2 h2f(unsigned raw) {
    return __half22float2(*(__half2*)&raw);
}

__device__ __forceinline__ unsigned f2h(float a, float b) {
    __half2 p = __floats2half2_rn(a, b);
    return *(unsigned*)&p;
}

__device__ __forceinline__ uint2 f4_to_h4(float a, float b, float c, float d) {
    uint2 u;
    u.x = f2h(a, b);
    u.y = f2h(c, d);
    return u;
}

// accumulate 8 halves (uint4) into acc[8], weighted / unweighted
__device__ __forceinline__ void acc8_w(float* acc, uint4 r, float wt) {
    float2 p0 = h2f(r.x), p1 = h2f(r.y), p2 = h2f(r.z), p3 = h2f(r.w);
    acc[0] = fmaf(wt, p0.x, acc[0]); acc[1] = fmaf(wt, p0.y, acc[1]);
    acc[2] = fmaf(wt, p1.x, acc[2]); acc[3] = fmaf(wt, p1.y, acc[3]);
    acc[4] = fmaf(wt, p2.x, acc[4]); acc[5] = fmaf(wt, p2.y, acc[5]);
    acc[6] = fmaf(wt, p3.x, acc[6]); acc[7] = fmaf(wt, p3.y, acc[7]);
}

__device__ __forceinline__ void acc8(float* acc, uint4 r) {
    float2 p0 = h2f(r.x), p1 = h2f(r.y), p2 = h2f(r.z), p3 = h2f(r.w);
    acc[0] += p0.x; acc[1] += p0.y; acc[2] += p1.x; acc[3] += p1.y;
    acc[4] += p2.x; acc[5] += p2.y; acc[6] += p3.x; acc[7] += p3.y;
}

__device__ __forceinline__ void mma16816(float* c, unsigned a0, unsigned a1,
                                         unsigned a2, unsigned a3,
                                         unsigned b0, unsigned b1) {
    asm volatile(
        "mma.sync.aligned.m16n8k16.row.col.f32.f16.f16.f32 "
        "{%0,%1,%2,%3}, {%4,%5,%6,%7}, {%8,%9}, {%0,%1,%2,%3};"
        : "+f"(c[0]), "+f"(c[1]), "+f"(c[2]), "+f"(c[3])
        : "r"(a0), "r"(a1), "r"(a2), "r"(a3), "r"(b0), "r"(b1));
}

// ------- in-degree histogram: 4 edges/thread, no-return atomics ------------
__global__ void k_cnt(const int* __restrict__ dst, int E) {
    if (blockIdx.x == 0 && threadIdx.x < NBLK_SCAN)
        g_lbFlag[threadIdx.x] = 0;
    int base = (blockIdx.x * blockDim.x + threadIdx.x) * 4;
    if (base + 3 < E) {
        int4 d4 = *(const int4*)(dst + base);
        red_add_i(&g_cntI[d4.x], 1);
        red_add_i(&g_cntI[d4.y], 1);
        red_add_i(&g_cntI[d4.z], 1);
        red_add_i(&g_cntI[d4.w], 1);
    } else {
        for (int e = base; e < E; e++)
            red_add_i(&g_cntI[dst[e]], 1);
    }
}

// ------- decoupled look-back scan + dinv + BN fold + resets ----------------
__global__ void __launch_bounds__(256) k_scanLB(
        const float* __restrict__ b1, const float* __restrict__ g1,
        const float* __restrict__ be1, const float* __restrict__ m1,
        const float* __restrict__ v1,
        const float* __restrict__ b2, const float* __restrict__ g2,
        const float* __restrict__ be2, const float* __restrict__ m2,
        const float* __restrict__ v2, int N, int E) {
    __shared__ int wsum[8];
    __shared__ unsigned exS;
    __shared__ int totS;
    int tid = threadIdx.x, bid = blockIdx.x;
    int lane = tid & 31, w = tid >> 5;
    int base = bid * 1024 + tid * 4;

    int v0 = 0, vv1 = 0, vv2 = 0, vv3 = 0;
    if (base + 0 < N) v0  = g_cntI[base + 0];
    if (base + 1 < N) vv1 = g_cntI[base + 1];
    if (base + 2 < N) vv2 = g_cntI[base + 2];
    if (base + 3 < N) vv3 = g_cntI[base + 3];
    int s = v0 + vv1 + vv2 + vv3;

    int inc = s;
#pragma unroll
    for (int o = 1; o < 32; o <<= 1) {
        int y = __shfl_up_sync(0xffffffff, inc, o);
        if (lane >= o) inc += y;
    }
    if (lane == 31) wsum[w] = inc;
    __syncthreads();
    if (tid == 0) {
        int run = 0;
#pragma unroll
        for (int i = 0; i < 8; i++) { int xv = wsum[i]; wsum[i] = run; run += xv; }
        totS = run;
        unsigned pack = (bid == 0 ? (2u << 30) : (1u << 30)) | (unsigned)run;
        atomicExch((unsigned*)&g_lbFlag[bid], pack);
    }
    __syncthreads();
    int blkEx = wsum[w] + inc - s;
    int total = totS;

    if (bid > 0) {
        if (w == 0) {
            unsigned ex = 0;
            int wnd = bid;
            for (;;) {
                int idx = wnd - 32 + lane;
                unsigned f = (1u << 30);
                if (idx >= 0) {
                    do { f = g_lbFlag[idx]; } while ((f >> 30) == 0);
                }
                unsigned isPref = __ballot_sync(0xffffffff, idx >= 0 && (f >> 30) == 2u);
                int cut = isPref ? (31 - __clz(isPref)) : -1;
                unsigned val = (lane >= cut) ? (f & 0x3FFFFFFFu) : 0u;
#pragma unroll
                for (int o = 16; o; o >>= 1) val += __shfl_down_sync(0xffffffff, val, o);
                if (lane == 0) ex += val;
                if (cut >= 0) break;
                wnd -= 32;
            }
            if (lane == 0) {
                exS = ex;
                atomicExch((unsigned*)&g_lbFlag[bid], (2u << 30) | (ex + (unsigned)total));
            }
        }
        __syncthreads();
    } else if (tid == 0) {
        exS = 0;
    }
    __syncthreads();
    unsigned ex = exS;

    int o = (int)ex + blkEx;
    if (base + 0 < N) { g_offs[base+0]=o; g_cursor[base+0]=o; g_dinv[base+0]=rsqrtf((float)v0 +1.f); g_cntI[base+0]=0; o+=v0;  }
    if (base + 1 < N) { g_offs[base+1]=o; g_cursor[base+1]=o; g_dinv[base+1]=rsqrtf((float)vv1+1.f); g_cntI[base+1]=0; o+=vv1; }
    if (base + 2 < N) { g_offs[base+2]=o; g_cursor[base+2]=o; g_dinv[base+2]=rsqrtf((float)vv2+1.f); g_cntI[base+2]=0; o+=vv2; }
    if (base + 3 < N) { g_offs[base+3]=o; g_cursor[base+3]=o; g_dinv[base+3]=rsqrtf((float)vv3+1.f); g_cntI[base+3]=0; }

    if (bid == 0 && tid == 0) g_offs[N] = E;
    if (bid == 0 && tid < D) {
        float s1 = g1[tid] * rsqrtf(v1[tid] + 1e-5f);
        g_sc1[tid] = s1;
        g_sh1[tid] = (b1[tid] - m1[tid]) * s1 + be1[tid];
        float s2 = g2[tid] * rsqrtf(v2[tid] + 1e-5f);
        g_sc2[tid] = s2;
        g_sh2[tid] = (b2[tid] - m2[tid]) * s2 + be2[tid];
    }
}

// ------- fill CSR: 4 edges/thread via int4 (MLP=4) -------------------------
__global__ void k_fill(const int* __restrict__ src, const int* __restrict__ dst, int E) {
    int base = (blockIdx.x * blockDim.x + threadIdx.x) * 4;
    if (base + 3 < E) {
        int4 d4 = *(const int4*)(dst + base);
        int4 s4 = *(const int4*)(src + base);
        int p0 = atomicAdd(&g_cursor[d4.x], 1);
        int p1 = atomicAdd(&g_cursor[d4.y], 1);
        int p2 = atomicAdd(&g_cursor[d4.z], 1);
        int p3 = atomicAdd(&g_cursor[d4.w], 1);
        g_csrc[p0] = s4.x;
        g_csrc[p1] = s4.y;
        g_csrc[p2] = s4.z;
        g_csrc[p3] = s4.w;
    } else {
        for (int e = base; e < E; e++) {
            int d = dst[e];
            int p = atomicAdd(&g_cursor[d], 1);
            g_csrc[p] = src[e];
        }
    }
}

// ---------------- GEMM1 core macro ----------------
#define GEMM_ROW(ai, i)                                                           \
    acc[i][0] = fmaf(ai.w, w3.x, fmaf(ai.z, w2.x, fmaf(ai.y, w1.x, fmaf(ai.x, w0.x, acc[i][0])))); \
    acc[i][1] = fmaf(ai.w, w3.y, fmaf(ai.z, w2.y, fmaf(ai.y, w1.y, fmaf(ai.x, w0.y, acc[i][1])))); \
    acc[i][2] = fmaf(ai.w, w3.z, fmaf(ai.z, w2.z, fmaf(ai.y, w1.z, fmaf(ai.x, w0.z, acc[i][2])))); \
    acc[i][3] = fmaf(ai.w, w3.w, fmaf(ai.z, w2.w, fmaf(ai.y, w1.w, fmaf(ai.x, w0.w, acc[i][3]))));

// ------- GEMM1: C_h[N,64] = fp16(A_f32 @ W1) (runs ∥ CSR chain) ------------
__global__ void __launch_bounds__(256) k_gemm1(const float* __restrict__ A,
                                               const float* __restrict__ W,
                                               __half* __restrict__ C, int N) {
    __shared__ __align__(16) float Ws[D * D];
    __shared__ __align__(16) float As[64 * 68];
    int tid = threadIdx.x;
    int row0 = blockIdx.x * 64;

    float4* Ws4 = (float4*)Ws;
    const float4* W4 = (const float4*)W;
#pragma unroll
    for (int i = 0; i < 4; i++) Ws4[tid + i * 256] = W4[tid + i * 256];

#pragma unroll
    for (int i = 0; i < 4; i++) {
        int idx = tid + i * 256;
        int r = idx >> 4, c4 = idx & 15;
        float4 a = make_float4(0.f, 0.f, 0.f, 0.f);
        if (row0 + r < N)
            a = __ldcs((const float4*)(A + (size_t)(row0 + r) * D) + c4);
        ((float4*)&As[r * 68])[c4] = a;
    }
    __syncthreads();

    int tx = tid & 15, ty = tid >> 4;
    float acc[4][4];
#pragma unroll
    for (int i = 0; i < 4; i++)
#pragma unroll
        for (int j = 0; j < 4; j++) acc[i][j] = 0.f;

    const float4* A0 = (const float4*)&As[(ty * 4 + 0) * 68];
    const float4* A1 = (const float4*)&As[(ty * 4 + 1) * 68];
    const float4* A2 = (const float4*)&As[(ty * 4 + 2) * 68];
    const float4* A3 = (const float4*)&As[(ty * 4 + 3) * 68];

#pragma unroll
    for (int k4 = 0; k4 < 16; k4++) {
        float4 w0 = Ws4[(4 * k4 + 0) * 16 + tx];
        float4 w1 = Ws4[(4 * k4 + 1) * 16 + tx];
        float4 w2 = Ws4[(4 * k4 + 2) * 16 + tx];
        float4 w3 = Ws4[(4 * k4 + 3) * 16 + tx];
        float4 a0 = A0[k4], a1 = A1[k4], a2 = A2[k4], a3 = A3[k4];
        GEMM_ROW(a0, 0)
        GEMM_ROW(a1, 1)
        GEMM_ROW(a2, 2)
        GEMM_ROW(a3, 3)
    }

#pragma unroll
    for (int i = 0; i < 4; i++) {
        int r = row0 + ty * 4 + i;
        if (r < N)
            ((uint2*)(C + (size_t)r * D))[tx] =
                f4_to_h4(acc[i][0], acc[i][1], acc[i][2], acc[i][3]);
    }
}

// -------- layer-1 gather: 8 threads/node, uint4 (16B) lanes ----------------
__global__ void __launch_bounds__(256) k_agg1(int N) {
    int t = blockIdx.x * blockDim.x + threadIdx.x;
    int node = t >> 3;
    if (node >= N) return;
    int c8 = t & 7;
    const uint4* hp = (const uint4*)g_hH;   // row = 8 uint4
    float dd = g_dinv[node];
    float acc[8];
    {
        uint4 sr = hp[(size_t)node * 8 + c8];
        float2 p0 = h2f(sr.x), p1 = h2f(sr.y), p2 = h2f(sr.z), p3 = h2f(sr.w);
        acc[0] = dd * p0.x; acc[1] = dd * p0.y;
        acc[2] = dd * p1.x; acc[3] = dd * p1.y;
        acc[4] = dd * p2.x; acc[5] = dd * p2.y;
        acc[6] = dd * p3.x; acc[7] = dd * p3.y;
    }
    int beg = g_offs[node], end = g_offs[node + 1];
    int j = beg;
    for (; j + 3 < end; j += 4) {
        int i0 = __ldg(&g_csrc[j + 0]);
        int i1 = __ldg(&g_csrc[j + 1]);
        int i2 = __ldg(&g_csrc[j + 2]);
        int i3 = __ldg(&g_csrc[j + 3]);
        float w0 = __ldg(&g_dinv[i0]);
        float w1 = __ldg(&g_dinv[i1]);
        float w2 = __ldg(&g_dinv[i2]);
        float w3 = __ldg(&g_dinv[i3]);
        uint4 r0 = __ldg(&hp[(size_t)i0 * 8 + c8]);
        uint4 r1 = __ldg(&hp[(size_t)i1 * 8 + c8]);
        uint4 r2 = __ldg(&hp[(size_t)i2 * 8 + c8]);
        uint4 r3 = __ldg(&hp[(size_t)i3 * 8 + c8]);
        acc8_w(acc, r0, w0);
        acc8_w(acc, r1, w1);
        acc8_w(acc, r2, w2);
        acc8_w(acc, r3, w3);
    }
    for (; j < end; j++) {
        int i0 = __ldg(&g_csrc[j]);
        float w0 = __ldg(&g_dinv[i0]);
        uint4 r0 = __ldg(&hp[(size_t)i0 * 8 + c8]);
        acc8_w(acc, r0, w0);
    }
    int c = c8 * 8;
    uint4 outv;
    {
        float y0 = fmaxf(0.f, acc[0] * dd * g_sc1[c + 0] + g_sh1[c + 0]);
        float y1 = fmaxf(0.f, acc[1] * dd * g_sc1[c + 1] + g_sh1[c + 1]);
        float y2 = fmaxf(0.f, acc[2] * dd * g_sc1[c + 2] + g_sh1[c + 2]);
        float y3 = fmaxf(0.f, acc[3] * dd * g_sc1[c + 3] + g_sh1[c + 3]);
        float y4 = fmaxf(0.f, acc[4] * dd * g_sc1[c + 4] + g_sh1[c + 4]);
        float y5 = fmaxf(0.f, acc[5] * dd * g_sc1[c + 5] + g_sh1[c + 5]);
        float y6 = fmaxf(0.f, acc[6] * dd * g_sc1[c + 6] + g_sh1[c + 6]);
        float y7 = fmaxf(0.f, acc[7] * dd * g_sc1[c + 7] + g_sh1[c + 7]);
        outv.x = f2h(y0, y1); outv.y = f2h(y2, y3);
        outv.z = f2h(y4, y5); outv.w = f2h(y6, y7);
    }
    ((uint4*)g_hG)[(size_t)node * 8 + c8] = outv;
}

// ------- GEMM2 tensor-core: hH = fp16((hG @ W2) * dinv), W2 split hi+res ---
__global__ void __launch_bounds__(256) k_gemm2tc(const __half* __restrict__ A,
                                                 const float* __restrict__ W,
                                                 __half* __restrict__ C, int N) {
    __shared__ __align__(16) __half As[128 * 72];
    __shared__ __align__(16) __half Wh[64 * 72];
    __shared__ __align__(16) __half Wr[64 * 72];
    int tid = threadIdx.x;
    int warp = tid >> 5, lane = tid & 31;
    int row0 = blockIdx.x * 128;

    // W2 -> fp16 hi + fp16 residual, transposed [n][k]
#pragma unroll
    for (int i = 0; i < 16; i++) {
        int idx = tid + i * 256;
        int k = idx >> 6, n = idx & 63;
        float w = W[k * 64 + n];
        __half wh = __float2half_rn(w);
        Wh[n * 72 + k] = wh;
        Wr[n * 72 + k] = __float2half_rn(w - __half2float(wh));
    }

    // A tile: 128 rows x 64 halves, row stride 72 halves
#pragma unroll
    for (int i = 0; i < 4; i++) {
        int idx = tid + i * 256;
        int r = idx >> 3, c8 = idx & 7;
        uint4 raw = make_uint4(0u, 0u, 0u, 0u);
        if (row0 + r < N)
            raw = __ldcs((const uint4*)(A + (size_t)(row0 + r) * D) + c8);
        *(uint4*)&As[r * 72 + c8 * 8] = raw;
    }
    __syncthreads();

    int g = lane >> 2, tg = lane & 3;
    int rbase = warp * 16;
    float acc[8][4];
#pragma unroll
    for (int nt = 0; nt < 8; nt++)
#pragma unroll
        for (int i = 0; i < 4; i++) acc[nt][i] = 0.f;

#pragma unroll
    for (int k0 = 0; k0 < 64; k0 += 16) {
        unsigned ra0 = *(const unsigned*)&As[(rbase + g) * 72 + k0 + tg * 2];
        unsigned ra1 = *(const unsigned*)&As[(rbase + g + 8) * 72 + k0 + tg * 2];
        unsigned ra2 = *(const unsigned*)&As[(rbase + g) * 72 + k0 + tg * 2 + 8];
        unsigned ra3 = *(const unsigned*)&As[(rbase + g + 8) * 72 + k0 + tg * 2 + 8];
#pragma unroll
        for (int nt = 0; nt < 8; nt++) {
            int nrow = (nt * 8 + g) * 72 + k0 + tg * 2;
            unsigned bh0 = *(const unsigned*)&Wh[nrow];
            unsigned bh1 = *(const unsigned*)&Wh[nrow + 8];
            mma16816(acc[nt], ra0, ra1, ra2, ra3, bh0, bh1);
            unsigned br0 = *(const unsigned*)&Wr[nrow];
            unsigned br1 = *(const unsigned*)&Wr[nrow + 8];
            mma16816(acc[nt], ra0, ra1, ra2, ra3, br0, br1);
        }
    }

    int r0g = row0 + rbase + g;
    int r1g = r0g + 8;
    float d0 = (r0g < N) ? g_dinv[r0g] : 0.f;
    float d1 = (r1g < N) ? g_dinv[r1g] : 0.f;
#pragma unroll
    for (int nt = 0; nt < 8; nt++) {
        int n = nt * 8 + tg * 2;
        if (r0g < N)
            *(unsigned*)(C + (size_t)r0g * D + n) = f2h(acc[nt][0] * d0, acc[nt][1] * d0);
        if (r1g < N)
            *(unsigned*)(C + (size_t)r1g * D + n) = f2h(acc[nt][2] * d1, acc[nt][3] * d1);
    }
}

// ------- agg2 (8T/node uint4) + BN2 + ReLU + pool + last-block classifier --
__global__ void __launch_bounds__(256) k_agg2cls(const int* __restrict__ batch,
                                                 const float* __restrict__ Wc,
                                                 const float* __restrict__ bc,
                                                 float* __restrict__ out, int N) {
    __shared__ int isLast;
    int t = blockIdx.x * blockDim.x + threadIdx.x;
    int tid = threadIdx.x;
    int node = t >> 3;
    if (node < N) {
        int c8 = t & 7;
        const uint4* hp = (const uint4*)g_hH;
        float acc[8];
        {
            uint4 sr = hp[(size_t)node * 8 + c8];
            float2 p0 = h2f(sr.x), p1 = h2f(sr.y), p2 = h2f(sr.z), p3 = h2f(sr.w);
            acc[0] = p0.x; acc[1] = p0.y; acc[2] = p1.x; acc[3] = p1.y;
            acc[4] = p2.x; acc[5] = p2.y; acc[6] = p3.x; acc[7] = p3.y;
        }
        int beg = g_offs[node], end = g_offs[node + 1];
        int j = beg;
        for (; j + 3 < end; j += 4) {
            int i0 = __ldg(&g_csrc[j + 0]);
            int i1 = __ldg(&g_csrc[j + 1]);
            int i2 = __ldg(&g_csrc[j + 2]);
            int i3 = __ldg(&g_csrc[j + 3]);
            uint4 r0 = __ldg(&hp[(size_t)i0 * 8 + c8]);
            uint4 r1 = __ldg(&hp[(size_t)i1 * 8 + c8]);
            uint4 r2 = __ldg(&hp[(size_t)i2 * 8 + c8]);
            uint4 r3 = __ldg(&hp[(size_t)i3 * 8 + c8]);
            acc8(acc, r0);
            acc8(acc, r1);
            acc8(acc, r2);
            acc8(acc, r3);
        }
        for (; j < end; j++) {
            int i0 = __ldg(&g_csrc[j]);
            uint4 r0 = __ldg(&hp[(size_t)i0 * 8 + c8]);
            acc8(acc, r0);
        }
        float dd = g_dinv[node];
        int c = c8 * 8;
        float y0 = fmaxf(0.f, acc[0] * dd * g_sc2[c + 0] + g_sh2[c + 0]);
        float y1 = fmaxf(0.f, acc[1] * dd * g_sc2[c + 1] + g_sh2[c + 1]);
        float y2 = fmaxf(0.f, acc[2] * dd * g_sc2[c + 2] + g_sh2[c + 2]);
        float y3 = fmaxf(0.f, acc[3] * dd * g_sc2[c + 3] + g_sh2[c + 3]);
        float y4 = fmaxf(0.f, acc[4] * dd * g_sc2[c + 4] + g_sh2[c + 4]);
        float y5 = fmaxf(0.f, acc[5] * dd * g_sc2[c + 5] + g_sh2[c + 5]);
        float y6 = fmaxf(0.f, acc[6] * dd * g_sc2[c + 6] + g_sh2[c + 6]);
        float y7 = fmaxf(0.f, acc[7] * dd * g_sc2[c + 7] + g_sh2[c + 7]);
        int g = batch[node];
        red_add_v4(&g_pooled[g * D + c + 0], y0, y1, y2, y3);
        red_add_v4(&g_pooled[g * D + c + 4], y4, y5, y6, y7);
        if (c8 == 0) atomicAdd(&g_cnt[g], 1.0f);
    }

    // last-block-does-classifier
    __threadfence();
    __syncthreads();
    if (tid == 0) {
        unsigned old = atomicAdd(&g_done, 1u);
        isLast = (old == gridDim.x - 1u) ? 1 : 0;
    }
    __syncthreads();
    if (isLast) {
        __threadfence();                      // acquire all blocks' reds
        if (tid < NGRAPH * 2) {
            int g = tid >> 1, o = tid & 1;
            float inv = 1.f / fmaxf(g_cnt[g], 1.f);
            float s = 0.f;
#pragma unroll
            for (int d = 0; d < D; d++) s += g_pooled[g * D + d] * Wc[d * 2 + o];
            out[tid] = s * inv + bc[o];
        }
        __syncthreads();
        for (int i = tid; i < NGRAPH * D; i += 256) g_pooled[i] = 0.f;
        if (tid < NGRAPH) g_cnt[tid] = 0.f;
        if (tid == 0) g_done = 0;
    }
}

// ---------------- host orchestration (fork/join, 7 launches) ---------------
extern "C" void kernel_launch(void* const* d_in, const int* in_sizes, int n_in,
                              void* d_out, int out_size) {
    const float* x   = (const float*)d_in[0];
    const int*   ei  = (const int*)d_in[1];
    const int*   bat = (const int*)d_in[2];
    const float* W1  = (const float*)d_in[3];
    const float* b1  = (const float*)d_in[4];
    const float* g1  = (const float*)d_in[5];
    const float* be1 = (const float*)d_in[6];
    const float* m1  = (const float*)d_in[7];
    const float* v1  = (const float*)d_in[8];
    const float* W2  = (const float*)d_in[9];
    const float* b2  = (const float*)d_in[10];
    const float* g2  = (const float*)d_in[11];
    const float* be2 = (const float*)d_in[12];
    const float* m2  = (const float*)d_in[13];
    const float* v2  = (const float*)d_in[14];
    const float* Wc  = (const float*)d_in[15];
    const float* bc  = (const float*)d_in[16];
    float* out = (float*)d_out;

    int N = in_sizes[0] / D;
    int E = in_sizes[1] / 2;
    const int* src = ei;
    const int* dst = ei + E;

    __half *hH, *hG;
    cudaGetSymbolAddress((void**)&hH, g_hH);
    cudaGetSymbolAddress((void**)&hG, g_hG);

    int nb_edges4 = (E + 1023) / 1024;
    int nb_node8  = (int)(((long long)N * 8 + 255) / 256);
    int nb_gemm1  = (N + 63) / 64;
    int nb_gemm2  = (N + 127) / 128;
    int nblk_scan = (N + 1023) / 1024;

    static cudaStream_t s2 = nullptr;
    static cudaEvent_t eFork = nullptr, eJoin = nullptr;
    if (!s2) {
        cudaStreamCreateWithFlags(&s2, cudaStreamNonBlocking);
        cudaEventCreateWithFlags(&eFork, cudaEventDisableTiming);
        cudaEventCreateWithFlags(&eJoin, cudaEventDisableTiming);
    }

    // fork: GEMM1 on s2 runs concurrently with CSR chain on default stream
    cudaEventRecord(eFork, 0);
    cudaStreamWaitEvent(s2, eFork, 0);
    k_gemm1<<<nb_gemm1, 256, 0, s2>>>(x, W1, hH, N);      // #1
    cudaEventRecord(eJoin, s2);

    k_cnt<<<nb_edges4, 256>>>(dst, E);                    // #2
    k_scanLB<<<nblk_scan, 256>>>(b1, g1, be1, m1, v1,
                                 b2, g2, be2, m2, v2, N, E); // #3
    k_fill<<<nb_edges4, 256>>>(src, dst, E);              // #4

    cudaStreamWaitEvent(0, eJoin, 0);                     // join

    // layer 1 gather + BN1 + ReLU (8 threads/node, uint4 lanes)
    k_agg1<<<nb_node8, 256>>>(N);                         // #5

    // layer 2: tensor-core GEMM(W2), dinv-scaled fp16 out
    k_gemm2tc<<<nb_gemm2, 256>>>(hG, W2, hH, N);          // #6

    // layer-2 gather + BN2 + ReLU + pool + fused classifier
    k_agg2cls<<<nb_node8, 256>>>(bat, Wc, bc, out, N);    // #7
}